// round 1
// baseline (speedup 1.0000x reference)
#include <cuda_runtime.h>
#include <math.h>

#define HID 2048
#define TT 1024
#define NH 32
#define HEAD 64

// ---------------- scratch (static device, no allocations) ----------------
__device__ float g_xn  [TT*HID];
__device__ float g_sx  [TT*HID];
__device__ float g_r   [TT*HID];
__device__ float g_k   [TT*HID];
__device__ float g_v   [TT*HID];
__device__ float g_w   [TT*HID];
__device__ float g_a   [TT*HID];
__device__ float g_g   [TT*HID];
__device__ float g_vmix[TT*HID];
__device__ float g_kk  [TT*HID];
__device__ float g_kka [TT*HID];
__device__ float g_y   [TT*HID];
__device__ float g_z   [TT*HID];
__device__ float g_wpre[TT*96];
__device__ float g_apre[TT*96];
__device__ float g_vpre[TT*64];
__device__ float g_gpre[TT*256];

// ---------------- helpers ----------------
__device__ __forceinline__ float warp_sum(float v) {
#pragma unroll
    for (int o = 16; o; o >>= 1) v += __shfl_xor_sync(0xffffffffu, v, o);
    return v;
}

// block-wide sum of two values, blockDim multiple of 32, <=256 threads
__device__ __forceinline__ void block_sum2(float& a, float& b, float* sbuf /*64 floats*/) {
#pragma unroll
    for (int o = 16; o; o >>= 1) {
        a += __shfl_xor_sync(0xffffffffu, a, o);
        b += __shfl_xor_sync(0xffffffffu, b, o);
    }
    int w = threadIdx.x >> 5, l = threadIdx.x & 31;
    int nw = blockDim.x >> 5;
    if (l == 0) { sbuf[w] = a; sbuf[32 + w] = b; }
    __syncthreads();
    if (threadIdx.x < 32) {
        float aa = (l < nw) ? sbuf[l] : 0.f;
        float bb = (l < nw) ? sbuf[32 + l] : 0.f;
#pragma unroll
        for (int o = 16; o; o >>= 1) {
            aa += __shfl_xor_sync(0xffffffffu, aa, o);
            bb += __shfl_xor_sync(0xffffffffu, bb, o);
        }
        if (l == 0) { sbuf[0] = aa; sbuf[32] = bb; }
    }
    __syncthreads();
    a = sbuf[0]; b = sbuf[32];
    __syncthreads();
}

// ---------------- K1: LayerNorm + token shift ----------------
__global__ void ln_shift_kernel(const float* __restrict__ x,
                                const float* __restrict__ state1,
                                const float* __restrict__ lnw,
                                const float* __restrict__ lnb,
                                float* __restrict__ xn, float* __restrict__ sx,
                                float* __restrict__ state1_out) {
    __shared__ float sbuf[64];
    int t = blockIdx.x;
    int tid = threadIdx.x;
    float cur[8], prv[8];
    float s = 0.f, s2 = 0.f, ps = 0.f, ps2 = 0.f;
    const float* xr = x + (size_t)t * HID;
#pragma unroll
    for (int i = 0; i < 8; i++) {
        int j = tid + i * 256;
        float v = xr[j]; cur[i] = v; s += v; s2 += v * v;
    }
    if (t > 0) {
        const float* xp = x + (size_t)(t - 1) * HID;
#pragma unroll
        for (int i = 0; i < 8; i++) {
            int j = tid + i * 256;
            float v = xp[j]; prv[i] = v; ps += v; ps2 += v * v;
        }
    }
    block_sum2(s, s2, sbuf);
    float mu = s * (1.f / HID);
    float var = s2 * (1.f / HID) - mu * mu;
    float rs = rsqrtf(var + 1e-5f);
    float pmu = 0.f, prs = 0.f;
    if (t > 0) {
        block_sum2(ps, ps2, sbuf);
        pmu = ps * (1.f / HID);
        float pv = ps2 * (1.f / HID) - pmu * pmu;
        prs = rsqrtf(pv + 1e-5f);
    }
#pragma unroll
    for (int i = 0; i < 8; i++) {
        int j = tid + i * 256;
        float c = (cur[i] - mu) * rs * lnw[j] + lnb[j];
        g_xn[(size_t)t * HID + j] = c;
        float p = (t > 0) ? ((prv[i] - pmu) * prs * lnw[j] + lnb[j]) : state1[j];
        g_sx[(size_t)t * HID + j] = p - c;
        if (t == TT - 1) state1_out[j] = c;
    }
}

// ---------------- GEMM 128x128x8, 256 threads, 8x8/thread ----------------
// C[M,N] = act(bias + A'[M,K] @ B[K,N]) (+ Cadd), where A' = A + coef[k]*Asx
// ACT: 0 none, 1 tanh, 2 sigmoid, 3 w-decay (exp(-0.606531*sigmoid))
template <int ACT>
__global__ void gemm128(const float* __restrict__ A, const float* __restrict__ Asx,
                        const float* __restrict__ coef,
                        const float* __restrict__ B,
                        const float* __restrict__ bias,
                        const float* __restrict__ Cadd,
                        float* __restrict__ C, int M, int N, int K) {
    __shared__ float As[8][128];
    __shared__ float Bs[8][128];
    int bm = blockIdx.y * 128;
    int bn = blockIdx.x * 128;
    int tid = threadIdx.x;
    int tx = tid & 15, ty = tid >> 4;
    float acc[8][8];
#pragma unroll
    for (int i = 0; i < 8; i++)
#pragma unroll
        for (int j = 0; j < 8; j++) acc[i][j] = 0.f;

    for (int k0 = 0; k0 < K; k0 += 8) {
#pragma unroll
        for (int i = 0; i < 4; i++) {
            int idx = tid + i * 256;
            int m = idx >> 3, kk = idx & 7;
            float av = A[(size_t)(bm + m) * K + k0 + kk];
            if (coef) av += coef[k0 + kk] * Asx[(size_t)(bm + m) * K + k0 + kk];
            As[kk][m] = av;
        }
#pragma unroll
        for (int i = 0; i < 4; i++) {
            int idx = tid + i * 256;
            int kk = idx >> 7, n = idx & 127;
            int gn = bn + n;
            Bs[kk][n] = (gn < N) ? B[(size_t)(k0 + kk) * N + gn] : 0.f;
        }
        __syncthreads();
#pragma unroll
        for (int kk = 0; kk < 8; kk++) {
            float a[8], b[8];
#pragma unroll
            for (int i = 0; i < 8; i++) a[i] = As[kk][ty * 8 + i];
#pragma unroll
            for (int j = 0; j < 8; j++) b[j] = Bs[kk][tx * 8 + j];
#pragma unroll
            for (int i = 0; i < 8; i++)
#pragma unroll
                for (int j = 0; j < 8; j++) acc[i][j] += a[i] * b[j];
        }
        __syncthreads();
    }
    int gm0 = bm + ty * 8;
    int gn0 = bn + tx * 8;
#pragma unroll
    for (int i = 0; i < 8; i++) {
#pragma unroll
        for (int j = 0; j < 8; j++) {
            int gn = gn0 + j;
            if (gn < N) {
                float v = acc[i][j];
                if (bias) v += bias[gn];
                if (ACT == 1) v = tanhf(v);
                else if (ACT == 2) v = 1.f / (1.f + expf(-v));
                else if (ACT == 3) { v = 1.f / (1.f + expf(-v)); v = expf(-0.606531f * v); }
                if (Cadd) v += Cadd[(size_t)(gm0 + i) * N + gn];
                C[(size_t)(gm0 + i) * N + gn] = v;
            }
        }
    }
}

// ---------------- small-N GEMM 64x32x16, 256 threads, 2x4/thread --------
// requires: M%64==0, N%32==0, K%16==0
template <int ACT>
__global__ void gemm_small(const float* __restrict__ A, const float* __restrict__ Asx,
                           const float* __restrict__ coef,
                           const float* __restrict__ B,
                           float* __restrict__ C, int M, int N, int K) {
    __shared__ float As[16][64];
    __shared__ float Bs[16][32];
    int bm = blockIdx.y * 64;
    int bn = blockIdx.x * 32;
    int tid = threadIdx.x;
    int tx = tid & 7, ty = tid >> 3;
    float acc[2][4];
#pragma unroll
    for (int i = 0; i < 2; i++)
#pragma unroll
        for (int j = 0; j < 4; j++) acc[i][j] = 0.f;

    for (int k0 = 0; k0 < K; k0 += 16) {
#pragma unroll
        for (int i = 0; i < 4; i++) {
            int idx = tid + i * 256;
            int m = idx >> 4, kk = idx & 15;
            float av = A[(size_t)(bm + m) * K + k0 + kk];
            if (coef) av += coef[k0 + kk] * Asx[(size_t)(bm + m) * K + k0 + kk];
            As[kk][m] = av;
        }
#pragma unroll
        for (int i = 0; i < 2; i++) {
            int idx = tid + i * 256;
            int kk = idx >> 5, n = idx & 31;
            Bs[kk][n] = B[(size_t)(k0 + kk) * N + bn + n];
        }
        __syncthreads();
#pragma unroll
        for (int kk = 0; kk < 16; kk++) {
            float a0 = As[kk][ty * 2 + 0];
            float a1 = As[kk][ty * 2 + 1];
            float b[4];
#pragma unroll
            for (int j = 0; j < 4; j++) b[j] = Bs[kk][tx * 4 + j];
#pragma unroll
            for (int j = 0; j < 4; j++) { acc[0][j] += a0 * b[j]; acc[1][j] += a1 * b[j]; }
        }
        __syncthreads();
    }
#pragma unroll
    for (int i = 0; i < 2; i++) {
#pragma unroll
        for (int j = 0; j < 4; j++) {
            float v = acc[i][j];
            if (ACT == 1) v = tanhf(v);
            else if (ACT == 2) v = 1.f / (1.f + expf(-v));
            C[(size_t)(bm + ty * 2 + i) * N + bn + tx * 4 + j] = v;
        }
    }
}

// ---------------- K5: per-head prep (kk norm, k modulation, v blend) ----
__global__ void prep_kernel(float* __restrict__ k, const float* __restrict__ a,
                            float* __restrict__ v, const float* __restrict__ v_first,
                            const float* __restrict__ vmix,
                            const float* __restrict__ k_k, const float* __restrict__ k_a,
                            float* __restrict__ kk, float* __restrict__ kka) {
    int hb = blockIdx.x;           // t*NH + h
    int t = hb >> 5, h = hb & 31;
    int l = threadIdx.x;           // 32
    int base = t * HID + h * HEAD;
    int hb0 = h * HEAD + l, hb1 = h * HEAD + l + 32;
    float k0 = k[base + l], k1 = k[base + 32 + l];
    float q0 = k0 * k_k[hb0], q1 = k1 * k_k[hb1];
    float ss = warp_sum(q0 * q0 + q1 * q1);
    float inv = 1.f / fmaxf(sqrtf(ss), 1e-12f);
    q0 *= inv; q1 *= inv;
    kk[base + l] = q0; kk[base + 32 + l] = q1;
    float a0 = a[base + l], a1 = a[base + 32 + l];
    kka[base + l] = q0 * a0; kka[base + 32 + l] = q1 * a1;
    k[base + l]      = k0 * (1.f + (a0 - 1.f) * k_a[hb0]);
    k[base + 32 + l] = k1 * (1.f + (a1 - 1.f) * k_a[hb1]);
    float v0 = v[base + l], v1 = v[base + 32 + l];
    v[base + l]      = v0 + (v_first[base + l]      - v0) * vmix[base + l];
    v[base + 32 + l] = v1 + (v_first[base + 32 + l] - v1) * vmix[base + 32 + l];
}

// ---------------- K6: sequential recurrence, 1 block per head ----------
__device__ __forceinline__ float rec_load(int idx, int gb,
        const float* __restrict__ wv, const float* __restrict__ kkv,
        const float* __restrict__ kkav, const float* __restrict__ kv,
        const float* __restrict__ vv, const float* __restrict__ rv) {
    int arr = idx >> 6, j = idx & 63;
    const float* p;
    switch (arr) {
        case 0: p = wv; break;
        case 1: p = kkv; break;
        case 2: p = kkav; break;
        case 3: p = kv; break;
        case 4: p = vv; break;
        default: p = rv; break;
    }
    return p[gb + j];
}

__global__ void recur_kernel(const float* __restrict__ S0,
                             const float* __restrict__ wv, const float* __restrict__ kkv,
                             const float* __restrict__ kkav, const float* __restrict__ kv,
                             const float* __restrict__ vv, const float* __restrict__ rv,
                             float* __restrict__ yout, float* __restrict__ S_out) {
    __shared__ __align__(16) float sh[384];
    int h = blockIdx.x;
    int tid = threadIdx.x;           // 256
    int row = tid >> 2;              // 0..63
    int q = tid & 3;                 // quarter
    int cb = q * 16;
    float s[16];
#pragma unroll
    for (int c = 0; c < 16; c++) s[c] = S0[h * 4096 + row * 64 + cb + c];

    int base0 = h * HEAD;
    float p0 = rec_load(tid, base0, wv, kkv, kkav, kv, vv, rv);
    float p1 = (tid < 128) ? rec_load(tid + 256, base0, wv, kkv, kkav, kv, vv, rv) : 0.f;

    for (int t = 0; t < TT; t++) {
        __syncthreads();
        sh[tid] = p0;
        if (tid < 128) sh[tid + 256] = p1;
        __syncthreads();
        if (t + 1 < TT) {
            int gb = (t + 1) * HID + base0;
            p0 = rec_load(tid, gb, wv, kkv, kkav, kv, vv, rv);
            if (tid < 128) p1 = rec_load(tid + 256, gb, wv, kkv, kkav, kv, vv, rv);
        }
        // sab_i = sum_j S[i,j]*kk[j]
        float sab = 0.f;
        {
            const float4* kk4 = (const float4*)(sh + 64 + cb);
#pragma unroll
            for (int u = 0; u < 4; u++) {
                float4 kq = kk4[u];
                sab += s[4 * u] * kq.x + s[4 * u + 1] * kq.y + s[4 * u + 2] * kq.z + s[4 * u + 3] * kq.w;
            }
        }
        sab += __shfl_xor_sync(0xffffffffu, sab, 1);
        sab += __shfl_xor_sync(0xffffffffu, sab, 2);
        float vi = sh[256 + row];
        float yy = 0.f;
        {
            const float4* w4 = (const float4*)(sh + cb);
            const float4* a4 = (const float4*)(sh + 128 + cb);
            const float4* k4 = (const float4*)(sh + 192 + cb);
            const float4* r4 = (const float4*)(sh + 320 + cb);
#pragma unroll
            for (int u = 0; u < 4; u++) {
                float4 wq = w4[u], aq = a4[u], kq = k4[u], rq = r4[u];
                s[4*u]   = s[4*u]   * wq.x - sab * aq.x + vi * kq.x; yy += s[4*u]   * rq.x;
                s[4*u+1] = s[4*u+1] * wq.y - sab * aq.y + vi * kq.y; yy += s[4*u+1] * rq.y;
                s[4*u+2] = s[4*u+2] * wq.z - sab * aq.z + vi * kq.z; yy += s[4*u+2] * rq.z;
                s[4*u+3] = s[4*u+3] * wq.w - sab * aq.w + vi * kq.w; yy += s[4*u+3] * rq.w;
            }
        }
        yy += __shfl_xor_sync(0xffffffffu, yy, 1);
        yy += __shfl_xor_sync(0xffffffffu, yy, 2);
        if (q == 0) yout[t * HID + base0 + row] = yy;
    }
#pragma unroll
    for (int c = 0; c < 16; c++) S_out[h * 4096 + row * 64 + cb + c] = s[c];
}

// ---------------- K7: per-head LN of y + rkv + gate ----------------
__global__ void post_kernel(const float* __restrict__ y, const float* __restrict__ r,
                            const float* __restrict__ k, const float* __restrict__ v,
                            const float* __restrict__ g, const float* __restrict__ r_k,
                            const float* __restrict__ lnw, const float* __restrict__ lnb,
                            float* __restrict__ z) {
    int hb = blockIdx.x;
    int t = hb >> 5, h = hb & 31;
    int l = threadIdx.x;       // 32
    int base = t * HID + h * HEAD;
    int hb0 = h * HEAD + l, hb1 = h * HEAD + l + 32;
    float y0 = y[base + l], y1 = y[base + 32 + l];
    float mu = warp_sum(y0 + y1) * (1.f / HEAD);
    float d0 = y0 - mu, d1 = y1 - mu;
    float var = warp_sum(d0 * d0 + d1 * d1) * (1.f / HEAD);
    float rs = rsqrtf(var + 0.00064f);
    float yn0 = d0 * rs * lnw[hb0] + lnb[hb0];
    float yn1 = d1 * rs * lnw[hb1] + lnb[hb1];
    float dot = warp_sum(r[base + l] * k[base + l] * r_k[hb0] +
                         r[base + 32 + l] * k[base + 32 + l] * r_k[hb1]);
    z[base + l]      = (yn0 + dot * v[base + l])      * g[base + l];
    z[base + 32 + l] = (yn1 + dot * v[base + 32 + l]) * g[base + 32 + l];
}

// ---------------- copy (v_first passthrough) ----------------
__global__ void copy4_kernel(const float4* __restrict__ src, float4* __restrict__ dst, int n4) {
    int i = blockIdx.x * blockDim.x + threadIdx.x;
    if (i < n4) dst[i] = src[i];
}

// ---------------- launch ----------------
extern "C" void kernel_launch(void* const* d_in, const int* in_sizes, int n_in,
                              void* d_out, int out_size) {
    const float* x       = (const float*)d_in[0];
    const float* state1  = (const float*)d_in[1];
    const float* state2  = (const float*)d_in[2];
    const float* v_first = (const float*)d_in[3];
    const float* ln1_w   = (const float*)d_in[4];
    const float* ln1_b   = (const float*)d_in[5];
    const float* x_r     = (const float*)d_in[6];
    const float* x_w     = (const float*)d_in[7];
    const float* x_k     = (const float*)d_in[8];
    const float* x_v     = (const float*)d_in[9];
    const float* x_a     = (const float*)d_in[10];
    const float* x_g     = (const float*)d_in[11];
    const float* Wr      = (const float*)d_in[12];
    const float* Wk      = (const float*)d_in[13];
    const float* Wv      = (const float*)d_in[14];
    const float* Wo      = (const float*)d_in[15];
    const float* w0      = (const float*)d_in[16];
    const float* w1      = (const float*)d_in[17];
    const float* w2      = (const float*)d_in[18];
    const float* a0      = (const float*)d_in[19];
    const float* a1      = (const float*)d_in[20];
    const float* a2      = (const float*)d_in[21];
    const float* v0      = (const float*)d_in[22];
    const float* v1      = (const float*)d_in[23];
    const float* v2      = (const float*)d_in[24];
    const float* g1      = (const float*)d_in[25];
    const float* g2      = (const float*)d_in[26];
    const float* k_k     = (const float*)d_in[27];
    const float* k_a     = (const float*)d_in[28];
    const float* r_k     = (const float*)d_in[29];
    const float* ln_x_w  = (const float*)d_in[30];
    const float* ln_x_b  = (const float*)d_in[31];

    float* out = (float*)d_out;
    float* out_main   = out;                         // 1024*2048
    float* out_state1 = out + 2097152;               // 2048
    float* out_S      = out + 2097152 + 2048;        // 32*64*64
    float* out_vfirst = out + 2097152 + 2048 + 131072;

    float *p_xn, *p_sx, *p_r, *p_k, *p_v, *p_w, *p_a, *p_g, *p_vmix, *p_kk, *p_kka, *p_y, *p_z;
    float *p_wpre, *p_apre, *p_vpre, *p_gpre;
    cudaGetSymbolAddress((void**)&p_xn, g_xn);
    cudaGetSymbolAddress((void**)&p_sx, g_sx);
    cudaGetSymbolAddress((void**)&p_r, g_r);
    cudaGetSymbolAddress((void**)&p_k, g_k);
    cudaGetSymbolAddress((void**)&p_v, g_v);
    cudaGetSymbolAddress((void**)&p_w, g_w);
    cudaGetSymbolAddress((void**)&p_a, g_a);
    cudaGetSymbolAddress((void**)&p_g, g_g);
    cudaGetSymbolAddress((void**)&p_vmix, g_vmix);
    cudaGetSymbolAddress((void**)&p_kk, g_kk);
    cudaGetSymbolAddress((void**)&p_kka, g_kka);
    cudaGetSymbolAddress((void**)&p_y, g_y);
    cudaGetSymbolAddress((void**)&p_z, g_z);
    cudaGetSymbolAddress((void**)&p_wpre, g_wpre);
    cudaGetSymbolAddress((void**)&p_apre, g_apre);
    cudaGetSymbolAddress((void**)&p_vpre, g_vpre);
    cudaGetSymbolAddress((void**)&p_gpre, g_gpre);

    // K1: LN + token shift (also writes state1_out)
    ln_shift_kernel<<<TT, 256>>>(x, state1, ln1_w, ln1_b, p_xn, p_sx, out_state1);

    // K2: big projections r,k,v
    dim3 gBig(16, 8);
    gemm128<0><<<gBig, 256>>>(p_xn, p_sx, x_r, Wr, nullptr, nullptr, p_r, TT, HID, HID);
    gemm128<0><<<gBig, 256>>>(p_xn, p_sx, x_k, Wk, nullptr, nullptr, p_k, TT, HID, HID);
    gemm128<0><<<gBig, 256>>>(p_xn, p_sx, x_v, Wv, nullptr, nullptr, p_v, TT, HID, HID);

    // K3: low-rank stage 1 (skinny N)
    gemm_small<1><<<dim3(96 / 32, 16), 256>>>(p_xn, p_sx, x_w, w1, p_wpre, TT, 96, HID);  // tanh
    gemm_small<0><<<dim3(96 / 32, 16), 256>>>(p_xn, p_sx, x_a, a1, p_apre, TT, 96, HID);
    gemm_small<0><<<dim3(64 / 32, 16), 256>>>(p_xn, p_sx, x_v, v1, p_vpre, TT, 64, HID);
    gemm_small<2><<<dim3(256 / 32, 16), 256>>>(p_xn, p_sx, x_g, g1, p_gpre, TT, 256, HID); // sigmoid

    // K4: low-rank stage 2 (wide N, small K)
    gemm128<3><<<gBig, 256>>>(p_wpre, nullptr, nullptr, w2, w0, nullptr, p_w, TT, HID, 96);    // decay
    gemm128<2><<<gBig, 256>>>(p_apre, nullptr, nullptr, a2, a0, nullptr, p_a, TT, HID, 96);    // sigmoid
    gemm128<2><<<gBig, 256>>>(p_vpre, nullptr, nullptr, v2, v0, nullptr, p_vmix, TT, HID, 64); // sigmoid
    gemm128<0><<<gBig, 256>>>(p_gpre, nullptr, nullptr, g2, nullptr, nullptr, p_g, TT, HID, 256);

    // K5: per-head prep
    prep_kernel<<<TT * NH, 32>>>(p_k, p_a, p_v, v_first, p_vmix, k_k, k_a, p_kk, p_kka);

    // K6: recurrence (writes S_final)
    recur_kernel<<<NH, 256>>>(state2, p_w, p_kk, p_kka, p_k, p_v, p_r, p_y, out_S);

    // K7: per-head LN + rkv + gate
    post_kernel<<<TT * NH, 32>>>(p_y, p_r, p_k, p_v, p_g, r_k, ln_x_w, ln_x_b, p_z);

    // K8: out = x + z @ Wo
    gemm128<0><<<gBig, 256>>>(p_z, nullptr, nullptr, Wo, nullptr, x, out_main, TT, HID, HID);

    // K9: v_first passthrough
    copy4_kernel<<<(524288 + 255) / 256, 256>>>((const float4*)v_first, (float4*)out_vfirst, 524288);

    (void)in_sizes; (void)n_in; (void)out_size;
}

// round 2
// speedup vs baseline: 2.2046x; 2.2046x over previous
#include <cuda_runtime.h>
#include <math.h>
#include <stdint.h>

#define HID 2048
#define TT 1024
#define NH 32
#define HEAD 64

// ---------------- scratch (static device, no allocations) ----------------
__device__ float g_mix[6][TT*HID];       // tf32-rounded: xr,xw,xk,xv,xa,xg
__device__ float g_wt[18874368];         // tf32-rounded weights
__device__ float g_r   [TT*HID];
__device__ float g_k   [TT*HID];
__device__ float g_v   [TT*HID];
__device__ float g_w   [TT*HID];
__device__ float g_a   [TT*HID];
__device__ float g_g   [TT*HID];
__device__ float g_vmix[TT*HID];
__device__ float g_kk  [TT*HID];
__device__ float g_kka [TT*HID];
__device__ float g_y   [TT*HID];
__device__ float g_z   [TT*HID];
__device__ float g_wpre[TT*96];
__device__ float g_apre[TT*96];
__device__ float g_vpre[TT*64];
__device__ float g_gpre[TT*256];

// weight offsets in g_wt (floats)
#define O_WR 0
#define O_WK 4194304
#define O_WV 8388608
#define O_WO 12582912
#define O_SM 16777216
#define O_W1 (O_SM + 0)
#define O_A1 (O_SM + 196608)
#define O_V1 (O_SM + 393216)
#define O_G1 (O_SM + 524288)
#define O_W2 (O_SM + 1048576)
#define O_A2 (O_SM + 1245184)
#define O_V2 (O_SM + 1441792)
#define O_G2 (O_SM + 1572864)

// ---------------- helpers ----------------
__device__ __forceinline__ float tf32r(float x) {
    float y;
    asm("cvt.rna.tf32.f32 %0, %1;" : "=f"(y) : "f"(x));
    return y;
}
__device__ __forceinline__ float warp_sum(float v) {
#pragma unroll
    for (int o = 16; o; o >>= 1) v += __shfl_xor_sync(0xffffffffu, v, o);
    return v;
}
__device__ __forceinline__ void block_sum2(float& a, float& b, float* sbuf) {
#pragma unroll
    for (int o = 16; o; o >>= 1) {
        a += __shfl_xor_sync(0xffffffffu, a, o);
        b += __shfl_xor_sync(0xffffffffu, b, o);
    }
    int w = threadIdx.x >> 5, l = threadIdx.x & 31;
    int nw = blockDim.x >> 5;
    if (l == 0) { sbuf[w] = a; sbuf[32 + w] = b; }
    __syncthreads();
    if (threadIdx.x < 32) {
        float aa = (l < nw) ? sbuf[l] : 0.f;
        float bb = (l < nw) ? sbuf[32 + l] : 0.f;
#pragma unroll
        for (int o = 16; o; o >>= 1) {
            aa += __shfl_xor_sync(0xffffffffu, aa, o);
            bb += __shfl_xor_sync(0xffffffffu, bb, o);
        }
        if (l == 0) { sbuf[0] = aa; sbuf[32] = bb; }
    }
    __syncthreads();
    a = sbuf[0]; b = sbuf[32];
    __syncthreads();
}

// ---------------- K0: weight round-to-tf32 ----------------
struct WList { const float* src[12]; int size[12]; int off[12]; };
__global__ void wcvt_kernel(WList wl) {
    int w = blockIdx.y;
    const float* s = wl.src[w];
    float* d = g_wt + wl.off[w];
    int n = wl.size[w];
    int stride = gridDim.x * blockDim.x;
    for (int i = blockIdx.x * blockDim.x + threadIdx.x; i < n; i += stride)
        d[i] = tf32r(s[i]);
}

// ---------------- K1: LayerNorm + token shift -> 6 rounded mixes --------
__global__ void ln_shift_kernel(const float* __restrict__ x,
                                const float* __restrict__ state1,
                                const float* __restrict__ lnw,
                                const float* __restrict__ lnb,
                                const float* __restrict__ c_r, const float* __restrict__ c_w,
                                const float* __restrict__ c_k, const float* __restrict__ c_v,
                                const float* __restrict__ c_a, const float* __restrict__ c_g,
                                float* __restrict__ state1_out) {
    __shared__ float sbuf[64];
    int t = blockIdx.x;
    int tid = threadIdx.x;
    float cur[8], prv[8];
    float s = 0.f, s2 = 0.f, ps = 0.f, ps2 = 0.f;
    const float* xr = x + (size_t)t * HID;
#pragma unroll
    for (int i = 0; i < 8; i++) {
        int j = tid + i * 256;
        float v = xr[j]; cur[i] = v; s += v; s2 += v * v;
    }
    if (t > 0) {
        const float* xp = x + (size_t)(t - 1) * HID;
#pragma unroll
        for (int i = 0; i < 8; i++) {
            int j = tid + i * 256;
            float v = xp[j]; prv[i] = v; ps += v; ps2 += v * v;
        }
    }
    block_sum2(s, s2, sbuf);
    float mu = s * (1.f / HID);
    float var = s2 * (1.f / HID) - mu * mu;
    float rs = rsqrtf(var + 1e-5f);
    float pmu = 0.f, prs = 0.f;
    if (t > 0) {
        block_sum2(ps, ps2, sbuf);
        pmu = ps * (1.f / HID);
        float pv = ps2 * (1.f / HID) - pmu * pmu;
        prs = rsqrtf(pv + 1e-5f);
    }
#pragma unroll
    for (int i = 0; i < 8; i++) {
        int j = tid + i * 256;
        float c = (cur[i] - mu) * rs * lnw[j] + lnb[j];
        float p = (t > 0) ? ((prv[i] - pmu) * prs * lnw[j] + lnb[j]) : state1[j];
        float sx = p - c;
        size_t o = (size_t)t * HID + j;
        g_mix[0][o] = tf32r(c + c_r[j] * sx);
        g_mix[1][o] = tf32r(c + c_w[j] * sx);
        g_mix[2][o] = tf32r(c + c_k[j] * sx);
        g_mix[3][o] = tf32r(c + c_v[j] * sx);
        g_mix[4][o] = tf32r(c + c_a[j] * sx);
        g_mix[5][o] = tf32r(c + c_g[j] * sx);
        if (t == TT - 1) state1_out[j] = c;
    }
}

// ---------------- tf32 tensor-core GEMM ----------------
// C[M,N] = act(bias + A[M,K] @ B[K,N]) (+ Cadd), A/B pre-rounded to tf32.
// 128x128 block tile, BK=16, 3-stage cp.async pipeline, 8 warps x (64x32).
#define BMT 128
#define BNT 128
#define BKT 16

__device__ __forceinline__ uint32_t smem_u32(const void* p) {
    return (uint32_t)__cvta_generic_to_shared(p);
}
__device__ __forceinline__ void cp16(uint32_t d, const float* s, bool pred) {
    int sz = pred ? 16 : 0;
    asm volatile("cp.async.cg.shared.global [%0], [%1], 16, %2;\n"
                 :: "r"(d), "l"(s), "r"(sz));
}
__device__ __forceinline__ void cp_commit() { asm volatile("cp.async.commit_group;\n" ::: "memory"); }
__device__ __forceinline__ void cp_wait2()  { asm volatile("cp.async.wait_group 2;\n" ::: "memory"); }

__device__ __forceinline__ void mma_tf32(float* c, const uint32_t* a, const uint32_t* b) {
    asm volatile("mma.sync.aligned.m16n8k8.row.col.f32.tf32.tf32.f32 "
                 "{%0,%1,%2,%3}, {%4,%5,%6,%7}, {%8,%9}, {%0,%1,%2,%3};"
                 : "+f"(c[0]), "+f"(c[1]), "+f"(c[2]), "+f"(c[3])
                 : "r"(a[0]), "r"(a[1]), "r"(a[2]), "r"(a[3]), "r"(b[0]), "r"(b[1]));
}

// ACT: 0 none, 1 tanh, 2 sigmoid, 3 decay exp(-0.606531*sigmoid)
template <int ACT, int ROUND>
__global__ void __launch_bounds__(256) gemm_tf32(
        const float* __restrict__ A, const float* __restrict__ B,
        const float* __restrict__ bias, const float* __restrict__ Cadd,
        float* __restrict__ C, int M, int N, int K) {
    __shared__ float As[3][BMT * BKT];
    __shared__ float Bs[3][BKT * BNT];
    int tid = threadIdx.x, lane = tid & 31, wid = tid >> 5;
    int wm = wid >> 2, wn = wid & 3;
    int g = lane >> 2, t4 = lane & 3;
    int bm = blockIdx.y * BMT, bn = blockIdx.x * BNT;

    // gmem->smem mapping
    int am = tid >> 2;            // 0..63
    int ak = (tid & 3) << 2;      // 0,4,8,12
    int bk = tid >> 5;            // 0..7
    int bn4 = (tid & 31) << 2;    // 0..124
    int a_dst0 = am * 16 + ((((ak >> 2) ^ (am >> 1)) & 3) << 2);
    int a_dst1 = (am + 64) * 16 + ((((ak >> 2) ^ ((am + 64) >> 1)) & 3) << 2);
    int b_dst0 = bk * 128 + (bn4 ^ (bk << 3));
    int b_dst1 = (bk + 8) * 128 + (bn4 ^ ((bk + 8) << 3));
    bool bpred = (bn + bn4) < N;
    const float* Abase = A + (size_t)(bm + am) * K + ak;
    const float* Bbase = B + (size_t)bk * N + bn + bn4;

    float acc[4][4][4];
#pragma unroll
    for (int i = 0; i < 4; i++)
#pragma unroll
        for (int j = 0; j < 4; j++)
#pragma unroll
            for (int r = 0; r < 4; r++) acc[i][j][r] = 0.f;

    int KT = K / BKT;
    // prologue: 3 stages
#pragma unroll
    for (int s = 0; s < 3; s++) {
        int k0 = s * BKT;
        cp16(smem_u32(&As[s][a_dst0]), Abase + k0, true);
        cp16(smem_u32(&As[s][a_dst1]), Abase + (size_t)64 * K + k0, true);
        cp16(smem_u32(&Bs[s][b_dst0]), Bbase + (size_t)k0 * N, bpred);
        cp16(smem_u32(&Bs[s][b_dst1]), Bbase + (size_t)(k0 + 8) * N, bpred);
        cp_commit();
    }

    for (int kt = 0; kt < KT; kt++) {
        cp_wait2();
        __syncthreads();
        int st = kt % 3;
        const float* as = As[st];
        const float* bs = Bs[st];
#pragma unroll
        for (int ks = 0; ks < BKT; ks += 8) {
            uint32_t af[4][4], bf[4][2];
#pragma unroll
            for (int i = 0; i < 4; i++) {
                int m0 = wm * 64 + 16 * i + g;
                int ro = m0 * 16 + t4;
                int sw = (m0 >> 1) & 3;
                int c0 = (((ks >> 2) + 0) ^ sw) << 2;
                int c1 = (((ks >> 2) + 1) ^ sw) << 2;
                af[i][0] = __float_as_uint(as[ro + c0]);
                af[i][1] = __float_as_uint(as[ro + 128 + c0]);
                af[i][2] = __float_as_uint(as[ro + c1]);
                af[i][3] = __float_as_uint(as[ro + 128 + c1]);
            }
#pragma unroll
            for (int j = 0; j < 4; j++) {
                int n0 = wn * 32 + 8 * j + g;
                int k0 = ks + t4, k1 = ks + t4 + 4;
                bf[j][0] = __float_as_uint(bs[k0 * 128 + (n0 ^ (k0 << 3))]);
                bf[j][1] = __float_as_uint(bs[k1 * 128 + (n0 ^ (k1 << 3))]);
            }
#pragma unroll
            for (int i = 0; i < 4; i++)
#pragma unroll
                for (int j = 0; j < 4; j++)
                    mma_tf32(acc[i][j], af[i], bf[j]);
        }
        __syncthreads();
        int kn = kt + 3;
        if (kn < KT) {
            int k0 = kn * BKT;
            cp16(smem_u32(&As[st][a_dst0]), Abase + k0, true);
            cp16(smem_u32(&As[st][a_dst1]), Abase + (size_t)64 * K + k0, true);
            cp16(smem_u32(&Bs[st][b_dst0]), Bbase + (size_t)k0 * N, bpred);
            cp16(smem_u32(&Bs[st][b_dst1]), Bbase + (size_t)(k0 + 8) * N, bpred);
        }
        cp_commit();
    }

    // epilogue
#pragma unroll
    for (int i = 0; i < 4; i++) {
        int r0 = bm + wm * 64 + 16 * i + g;
#pragma unroll
        for (int rr = 0; rr < 2; rr++) {
            int row = r0 + rr * 8;
#pragma unroll
            for (int j = 0; j < 4; j++) {
                int col = bn + wn * 32 + 8 * j + 2 * t4;
                if (col < N) {
                    float v0 = acc[i][j][rr * 2 + 0];
                    float v1 = acc[i][j][rr * 2 + 1];
                    if (bias) { v0 += bias[col]; v1 += bias[col + 1]; }
                    if (ACT == 1) { v0 = tanhf(v0); v1 = tanhf(v1); }
                    else if (ACT == 2) {
                        v0 = 1.f / (1.f + expf(-v0));
                        v1 = 1.f / (1.f + expf(-v1));
                    } else if (ACT == 3) {
                        v0 = expf(-0.606531f / (1.f + expf(-v0)));
                        v1 = expf(-0.606531f / (1.f + expf(-v1)));
                    }
                    if (Cadd) {
                        v0 += Cadd[(size_t)row * N + col];
                        v1 += Cadd[(size_t)row * N + col + 1];
                    }
                    if (ROUND) { v0 = tf32r(v0); v1 = tf32r(v1); }
                    *(float2*)&C[(size_t)row * N + col] = make_float2(v0, v1);
                }
            }
        }
    }
}

// ---------------- K5: per-head prep ----------------
__global__ void prep_kernel(float* __restrict__ k, const float* __restrict__ a,
                            float* __restrict__ v, const float* __restrict__ v_first,
                            const float* __restrict__ vmix,
                            const float* __restrict__ k_k, const float* __restrict__ k_a,
                            float* __restrict__ kk, float* __restrict__ kka) {
    int hb = blockIdx.x;
    int t = hb >> 5, h = hb & 31;
    int l = threadIdx.x;
    int base = t * HID + h * HEAD;
    int hb0 = h * HEAD + l, hb1 = h * HEAD + l + 32;
    float k0 = k[base + l], k1 = k[base + 32 + l];
    float q0 = k0 * k_k[hb0], q1 = k1 * k_k[hb1];
    float ss = warp_sum(q0 * q0 + q1 * q1);
    float inv = 1.f / fmaxf(sqrtf(ss), 1e-12f);
    q0 *= inv; q1 *= inv;
    kk[base + l] = q0; kk[base + 32 + l] = q1;
    float a0 = a[base + l], a1 = a[base + 32 + l];
    kka[base + l] = q0 * a0; kka[base + 32 + l] = q1 * a1;
    k[base + l]      = k0 * (1.f + (a0 - 1.f) * k_a[hb0]);
    k[base + 32 + l] = k1 * (1.f + (a1 - 1.f) * k_a[hb1]);
    float v0 = v[base + l], v1 = v[base + 32 + l];
    v[base + l]      = v0 + (v_first[base + l]      - v0) * vmix[base + l];
    v[base + 32 + l] = v1 + (v_first[base + 32 + l] - v1) * vmix[base + 32 + l];
}

// ---------------- K6: sequential recurrence ----------------
__device__ __forceinline__ float rec_load(int idx, int gb,
        const float* __restrict__ wv, const float* __restrict__ kkv,
        const float* __restrict__ kkav, const float* __restrict__ kv,
        const float* __restrict__ vv, const float* __restrict__ rv) {
    int arr = idx >> 6, j = idx & 63;
    const float* p;
    switch (arr) {
        case 0: p = wv; break;
        case 1: p = kkv; break;
        case 2: p = kkav; break;
        case 3: p = kv; break;
        case 4: p = vv; break;
        default: p = rv; break;
    }
    return p[gb + j];
}

__global__ void recur_kernel(const float* __restrict__ S0,
                             const float* __restrict__ wv, const float* __restrict__ kkv,
                             const float* __restrict__ kkav, const float* __restrict__ kv,
                             const float* __restrict__ vv, const float* __restrict__ rv,
                             float* __restrict__ yout, float* __restrict__ S_out) {
    __shared__ __align__(16) float sh[384];
    int h = blockIdx.x;
    int tid = threadIdx.x;
    int row = tid >> 2;
    int q = tid & 3;
    int cb = q * 16;
    float s[16];
#pragma unroll
    for (int c = 0; c < 16; c++) s[c] = S0[h * 4096 + row * 64 + cb + c];

    int base0 = h * HEAD;
    float p0 = rec_load(tid, base0, wv, kkv, kkav, kv, vv, rv);
    float p1 = (tid < 128) ? rec_load(tid + 256, base0, wv, kkv, kkav, kv, vv, rv) : 0.f;

    for (int t = 0; t < TT; t++) {
        __syncthreads();
        sh[tid] = p0;
        if (tid < 128) sh[tid + 256] = p1;
        __syncthreads();
        if (t + 1 < TT) {
            int gb = (t + 1) * HID + base0;
            p0 = rec_load(tid, gb, wv, kkv, kkav, kv, vv, rv);
            if (tid < 128) p1 = rec_load(tid + 256, gb, wv, kkv, kkav, kv, vv, rv);
        }
        float sab = 0.f;
        {
            const float4* kk4 = (const float4*)(sh + 64 + cb);
#pragma unroll
            for (int u = 0; u < 4; u++) {
                float4 kq = kk4[u];
                sab += s[4 * u] * kq.x + s[4 * u + 1] * kq.y + s[4 * u + 2] * kq.z + s[4 * u + 3] * kq.w;
            }
        }
        sab += __shfl_xor_sync(0xffffffffu, sab, 1);
        sab += __shfl_xor_sync(0xffffffffu, sab, 2);
        float vi = sh[256 + row];
        float yy = 0.f;
        {
            const float4* w4 = (const float4*)(sh + cb);
            const float4* a4 = (const float4*)(sh + 128 + cb);
            const float4* k4 = (const float4*)(sh + 192 + cb);
            const float4* r4 = (const float4*)(sh + 320 + cb);
#pragma unroll
            for (int u = 0; u < 4; u++) {
                float4 wq = w4[u], aq = a4[u], kq = k4[u], rq = r4[u];
                s[4*u]   = s[4*u]   * wq.x - sab * aq.x + vi * kq.x; yy += s[4*u]   * rq.x;
                s[4*u+1] = s[4*u+1] * wq.y - sab * aq.y + vi * kq.y; yy += s[4*u+1] * rq.y;
                s[4*u+2] = s[4*u+2] * wq.z - sab * aq.z + vi * kq.z; yy += s[4*u+2] * rq.z;
                s[4*u+3] = s[4*u+3] * wq.w - sab * aq.w + vi * kq.w; yy += s[4*u+3] * rq.w;
            }
        }
        yy += __shfl_xor_sync(0xffffffffu, yy, 1);
        yy += __shfl_xor_sync(0xffffffffu, yy, 2);
        if (q == 0) yout[t * HID + base0 + row] = yy;
    }
#pragma unroll
    for (int c = 0; c < 16; c++) S_out[h * 4096 + row * 64 + cb + c] = s[c];
}

// ---------------- K7: per-head LN + rkv + gate (writes rounded z) -------
__global__ void post_kernel(const float* __restrict__ y, const float* __restrict__ r,
                            const float* __restrict__ k, const float* __restrict__ v,
                            const float* __restrict__ g, const float* __restrict__ r_k,
                            const float* __restrict__ lnw, const float* __restrict__ lnb,
                            float* __restrict__ z) {
    int hb = blockIdx.x;
    int t = hb >> 5, h = hb & 31;
    int l = threadIdx.x;
    int base = t * HID + h * HEAD;
    int hb0 = h * HEAD + l, hb1 = h * HEAD + l + 32;
    float y0 = y[base + l], y1 = y[base + 32 + l];
    float mu = warp_sum(y0 + y1) * (1.f / HEAD);
    float d0 = y0 - mu, d1 = y1 - mu;
    float var = warp_sum(d0 * d0 + d1 * d1) * (1.f / HEAD);
    float rs = rsqrtf(var + 0.00064f);
    float yn0 = d0 * rs * lnw[hb0] + lnb[hb0];
    float yn1 = d1 * rs * lnw[hb1] + lnb[hb1];
    float dot = warp_sum(r[base + l] * k[base + l] * r_k[hb0] +
                         r[base + 32 + l] * k[base + 32 + l] * r_k[hb1]);
    z[base + l]      = tf32r((yn0 + dot * v[base + l])      * g[base + l]);
    z[base + 32 + l] = tf32r((yn1 + dot * v[base + 32 + l]) * g[base + 32 + l]);
}

// ---------------- copy (v_first passthrough) ----------------
__global__ void copy4_kernel(const float4* __restrict__ src, float4* __restrict__ dst, int n4) {
    int i = blockIdx.x * blockDim.x + threadIdx.x;
    if (i < n4) dst[i] = src[i];
}

// ---------------- launch ----------------
extern "C" void kernel_launch(void* const* d_in, const int* in_sizes, int n_in,
                              void* d_out, int out_size) {
    const float* x       = (const float*)d_in[0];
    const float* state1  = (const float*)d_in[1];
    const float* state2  = (const float*)d_in[2];
    const float* v_first = (const float*)d_in[3];
    const float* ln1_w   = (const float*)d_in[4];
    const float* ln1_b   = (const float*)d_in[5];
    const float* x_r     = (const float*)d_in[6];
    const float* x_w     = (const float*)d_in[7];
    const float* x_k     = (const float*)d_in[8];
    const float* x_v     = (const float*)d_in[9];
    const float* x_a     = (const float*)d_in[10];
    const float* x_g     = (const float*)d_in[11];
    const float* Wr      = (const float*)d_in[12];
    const float* Wk      = (const float*)d_in[13];
    const float* Wv      = (const float*)d_in[14];
    const float* Wo      = (const float*)d_in[15];
    const float* w0      = (const float*)d_in[16];
    const float* w1      = (const float*)d_in[17];
    const float* w2      = (const float*)d_in[18];
    const float* a0      = (const float*)d_in[19];
    const float* a1      = (const float*)d_in[20];
    const float* a2      = (const float*)d_in[21];
    const float* v0      = (const float*)d_in[22];
    const float* v1      = (const float*)d_in[23];
    const float* v2      = (const float*)d_in[24];
    const float* g1      = (const float*)d_in[25];
    const float* g2      = (const float*)d_in[26];
    const float* k_k     = (const float*)d_in[27];
    const float* k_a     = (const float*)d_in[28];
    const float* r_k     = (const float*)d_in[29];
    const float* ln_x_w  = (const float*)d_in[30];
    const float* ln_x_b  = (const float*)d_in[31];

    float* out = (float*)d_out;
    float* out_main   = out;
    float* out_state1 = out + 2097152;
    float* out_S      = out + 2097152 + 2048;
    float* out_vfirst = out + 2097152 + 2048 + 131072;

    float *p_wt, *p_mix;
    float *p_r, *p_k, *p_v, *p_w, *p_a, *p_g, *p_vmix, *p_kk, *p_kka, *p_y, *p_z;
    float *p_wpre, *p_apre, *p_vpre, *p_gpre;
    cudaGetSymbolAddress((void**)&p_wt, g_wt);
    cudaGetSymbolAddress((void**)&p_mix, g_mix);
    cudaGetSymbolAddress((void**)&p_r, g_r);
    cudaGetSymbolAddress((void**)&p_k, g_k);
    cudaGetSymbolAddress((void**)&p_v, g_v);
    cudaGetSymbolAddress((void**)&p_w, g_w);
    cudaGetSymbolAddress((void**)&p_a, g_a);
    cudaGetSymbolAddress((void**)&p_g, g_g);
    cudaGetSymbolAddress((void**)&p_vmix, g_vmix);
    cudaGetSymbolAddress((void**)&p_kk, g_kk);
    cudaGetSymbolAddress((void**)&p_kka, g_kka);
    cudaGetSymbolAddress((void**)&p_y, g_y);
    cudaGetSymbolAddress((void**)&p_z, g_z);
    cudaGetSymbolAddress((void**)&p_wpre, g_wpre);
    cudaGetSymbolAddress((void**)&p_apre, g_apre);
    cudaGetSymbolAddress((void**)&p_vpre, g_vpre);
    cudaGetSymbolAddress((void**)&p_gpre, g_gpre);

    float* mixp[6];
    for (int i = 0; i < 6; i++) mixp[i] = p_mix + (size_t)i * TT * HID;

    // weight conversion list
    WList wl;
    const float* wsrc[12] = {Wr, Wk, Wv, Wo, w1, a1, v1, g1, w2, a2, v2, g2};
    int wsz[12] = {4194304, 4194304, 4194304, 4194304,
                   196608, 196608, 131072, 524288,
                   196608, 196608, 131072, 524288};
    int woff[12] = {O_WR, O_WK, O_WV, O_WO, O_W1, O_A1, O_V1, O_G1, O_W2, O_A2, O_V2, O_G2};
    for (int i = 0; i < 12; i++) { wl.src[i] = wsrc[i]; wl.size[i] = wsz[i]; wl.off[i] = woff[i]; }

    // K0 + K1
    wcvt_kernel<<<dim3(256, 12), 256>>>(wl);
    ln_shift_kernel<<<TT, 256>>>(x, state1, ln1_w, ln1_b,
                                 x_r, x_w, x_k, x_v, x_a, x_g, out_state1);

    dim3 gBig(16, 8);
    // big projections
    gemm_tf32<0,0><<<gBig, 256>>>(mixp[0], p_wt + O_WR, nullptr, nullptr, p_r, TT, HID, HID);
    gemm_tf32<0,0><<<gBig, 256>>>(mixp[2], p_wt + O_WK, nullptr, nullptr, p_k, TT, HID, HID);
    gemm_tf32<0,0><<<gBig, 256>>>(mixp[3], p_wt + O_WV, nullptr, nullptr, p_v, TT, HID, HID);

    // low-rank stage 1 (outputs rounded)
    gemm_tf32<1,1><<<dim3(1, 8), 256>>>(mixp[1], p_wt + O_W1, nullptr, nullptr, p_wpre, TT, 96, HID);
    gemm_tf32<0,1><<<dim3(1, 8), 256>>>(mixp[4], p_wt + O_A1, nullptr, nullptr, p_apre, TT, 96, HID);
    gemm_tf32<0,1><<<dim3(1, 8), 256>>>(mixp[3], p_wt + O_V1, nullptr, nullptr, p_vpre, TT, 64, HID);
    gemm_tf32<2,1><<<dim3(2, 8), 256>>>(mixp[5], p_wt + O_G1, nullptr, nullptr, p_gpre, TT, 256, HID);

    // low-rank stage 2
    gemm_tf32<3,0><<<gBig, 256>>>(p_wpre, p_wt + O_W2, w0, nullptr, p_w, TT, HID, 96);
    gemm_tf32<2,0><<<gBig, 256>>>(p_apre, p_wt + O_A2, a0, nullptr, p_a, TT, HID, 96);
    gemm_tf32<2,0><<<gBig, 256>>>(p_vpre, p_wt + O_V2, v0, nullptr, p_vmix, TT, HID, 64);
    gemm_tf32<0,0><<<gBig, 256>>>(p_gpre, p_wt + O_G2, nullptr, nullptr, p_g, TT, HID, 256);

    // per-head prep, recurrence, post
    prep_kernel<<<TT * NH, 32>>>(p_k, p_a, p_v, v_first, p_vmix, k_k, k_a, p_kk, p_kka);
    recur_kernel<<<NH, 256>>>(state2, p_w, p_kk, p_kka, p_k, p_v, p_r, p_y, out_S);
    post_kernel<<<TT * NH, 32>>>(p_y, p_r, p_k, p_v, p_g, r_k, ln_x_w, ln_x_b, p_z);

    // out = x + z @ Wo
    gemm_tf32<0,0><<<gBig, 256>>>(p_z, p_wt + O_WO, nullptr, x, out_main, TT, HID, HID);

    // v_first passthrough
    copy4_kernel<<<(524288 + 255) / 256, 256>>>((const float4*)v_first, (float4*)out_vfirst, 524288);

    (void)in_sizes; (void)n_in; (void)out_size;
}

// round 4
// speedup vs baseline: 2.6137x; 1.1856x over previous
#include <cuda_runtime.h>
#include <math.h>
#include <stdint.h>

#define HID 2048
#define TT 1024
#define NH 32
#define HEAD 64

// ---------------- scratch (static device, no allocations) ----------------
__device__ float g_mix[6][TT*HID];       // tf32-rounded: xr,xw,xk,xv,xa,xg
__device__ float g_part[2097152];        // stage-1 splitK partials
__device__ float g_r   [TT*HID];
__device__ float g_k   [TT*HID];
__device__ float g_v   [TT*HID];
__device__ float g_w   [TT*HID];
__device__ float g_a   [TT*HID];
__device__ float g_g   [TT*HID];
__device__ float g_vmix[TT*HID];
__device__ float g_kk  [TT*HID];
__device__ float g_kka [TT*HID];
__device__ float g_y   [TT*HID];
__device__ float g_z   [TT*HID];
__device__ float g_wpre[TT*96];
__device__ float g_apre[TT*96];
__device__ float g_vpre[TT*64];
__device__ float g_gpre[TT*256];

// part offsets (floats): KZ=4 chunks each
#define PW 0
#define PA 393216
#define PV 786432
#define PG 1048576

// ---------------- helpers ----------------
typedef unsigned long long u64;
__device__ __forceinline__ float tf32r(float x) {
    float y;
    asm("cvt.rna.tf32.f32 %0, %1;" : "=f"(y) : "f"(x));
    return y;
}
__device__ __forceinline__ u64 fma2(u64 a, u64 b, u64 c) {
    u64 d; asm("fma.rn.f32x2 %0,%1,%2,%3;" : "=l"(d) : "l"(a), "l"(b), "l"(c)); return d;
}
__device__ __forceinline__ u64 mul2(u64 a, u64 b) {
    u64 d; asm("mul.rn.f32x2 %0,%1,%2;" : "=l"(d) : "l"(a), "l"(b)); return d;
}
__device__ __forceinline__ u64 dup2(float x) {
    u64 d; asm("mov.b64 %0,{%1,%1};" : "=l"(d) : "f"(x)); return d;
}
__device__ __forceinline__ float2 unpk(u64 a) {
    float lo, hi; asm("mov.b64 {%0,%1},%2;" : "=f"(lo), "=f"(hi) : "l"(a));
    return make_float2(lo, hi);
}
__device__ __forceinline__ float warp_sum(float v) {
#pragma unroll
    for (int o = 16; o; o >>= 1) v += __shfl_xor_sync(0xffffffffu, v, o);
    return v;
}
__device__ __forceinline__ void block_sum2(float& a, float& b, float* sbuf) {
#pragma unroll
    for (int o = 16; o; o >>= 1) {
        a += __shfl_xor_sync(0xffffffffu, a, o);
        b += __shfl_xor_sync(0xffffffffu, b, o);
    }
    int w = threadIdx.x >> 5, l = threadIdx.x & 31;
    int nw = blockDim.x >> 5;
    if (l == 0) { sbuf[w] = a; sbuf[32 + w] = b; }
    __syncthreads();
    if (threadIdx.x < 32) {
        float aa = (l < nw) ? sbuf[l] : 0.f;
        float bb = (l < nw) ? sbuf[32 + l] : 0.f;
#pragma unroll
        for (int o = 16; o; o >>= 1) {
            aa += __shfl_xor_sync(0xffffffffu, aa, o);
            bb += __shfl_xor_sync(0xffffffffu, bb, o);
        }
        if (l == 0) { sbuf[0] = aa; sbuf[32] = bb; }
    }
    __syncthreads();
    a = sbuf[0]; b = sbuf[32];
    __syncthreads();
}

// ---------------- K1: LayerNorm + token shift -> 6 rounded mixes --------
__global__ void ln_shift_kernel(const float* __restrict__ x,
                                const float* __restrict__ state1,
                                const float* __restrict__ lnw,
                                const float* __restrict__ lnb,
                                const float* __restrict__ c_r, const float* __restrict__ c_w,
                                const float* __restrict__ c_k, const float* __restrict__ c_v,
                                const float* __restrict__ c_a, const float* __restrict__ c_g,
                                float* __restrict__ state1_out) {
    __shared__ float sbuf[64];
    int t = blockIdx.x;
    int tid = threadIdx.x;
    float cur[8], prv[8];
    float s = 0.f, s2 = 0.f, ps = 0.f, ps2 = 0.f;
    const float* xr = x + (size_t)t * HID;
#pragma unroll
    for (int i = 0; i < 8; i++) {
        int j = tid + i * 256;
        float v = xr[j]; cur[i] = v; s += v; s2 += v * v;
    }
    if (t > 0) {
        const float* xp = x + (size_t)(t - 1) * HID;
#pragma unroll
        for (int i = 0; i < 8; i++) {
            int j = tid + i * 256;
            float v = xp[j]; prv[i] = v; ps += v; ps2 += v * v;
        }
    }
    block_sum2(s, s2, sbuf);
    float mu = s * (1.f / HID);
    float var = s2 * (1.f / HID) - mu * mu;
    float rs = rsqrtf(var + 1e-5f);
    float pmu = 0.f, prs = 0.f;
    if (t > 0) {
        block_sum2(ps, ps2, sbuf);
        pmu = ps * (1.f / HID);
        float pv = ps2 * (1.f / HID) - pmu * pmu;
        prs = rsqrtf(pv + 1e-5f);
    }
#pragma unroll
    for (int i = 0; i < 8; i++) {
        int j = tid + i * 256;
        float c = (cur[i] - mu) * rs * lnw[j] + lnb[j];
        float p = (t > 0) ? ((prv[i] - pmu) * prs * lnw[j] + lnb[j]) : state1[j];
        float sx = p - c;
        size_t o = (size_t)t * HID + j;
        g_mix[0][o] = tf32r(c + c_r[j] * sx);
        g_mix[1][o] = tf32r(c + c_w[j] * sx);
        g_mix[2][o] = tf32r(c + c_k[j] * sx);
        g_mix[3][o] = tf32r(c + c_v[j] * sx);
        g_mix[4][o] = tf32r(c + c_a[j] * sx);
        g_mix[5][o] = tf32r(c + c_g[j] * sx);
        if (t == TT - 1) state1_out[j] = c;
    }
}

// ---------------- tf32 tensor-core GEMM ----------------
// C[M,N] = act(bias + A[M,K] @ B[K,N]) (+ Cadd).
// A pre-rounded to tf32; B rounded in-register after LDS (RNA).
// 128x128 tile, BK=16, 3-stage cp.async, 8 warps x (64x32).
// SplitK: gridDim.z chunks of `K` each (kchunk element stride), C offset bz*M*N.
#define BMT 128
#define BNT 128
#define BKT 16

__device__ __forceinline__ uint32_t smem_u32(const void* p) {
    return (uint32_t)__cvta_generic_to_shared(p);
}
__device__ __forceinline__ void cp16(uint32_t d, const float* s, bool pred) {
    int sz = pred ? 16 : 0;
    asm volatile("cp.async.cg.shared.global [%0], [%1], 16, %2;\n"
                 :: "r"(d), "l"(s), "r"(sz));
}
__device__ __forceinline__ void cp_commit() { asm volatile("cp.async.commit_group;\n" ::: "memory"); }
__device__ __forceinline__ void cp_wait2()  { asm volatile("cp.async.wait_group 2;\n" ::: "memory"); }

__device__ __forceinline__ void mma_tf32(float* c, const uint32_t* a, const uint32_t* b) {
    asm volatile("mma.sync.aligned.m16n8k8.row.col.f32.tf32.tf32.f32 "
                 "{%0,%1,%2,%3}, {%4,%5,%6,%7}, {%8,%9}, {%0,%1,%2,%3};"
                 : "+f"(c[0]), "+f"(c[1]), "+f"(c[2]), "+f"(c[3])
                 : "r"(a[0]), "r"(a[1]), "r"(a[2]), "r"(a[3]), "r"(b[0]), "r"(b[1]));
}

// ACT: 0 none, 1 tanh, 2 sigmoid, 3 decay exp(-0.606531*sigmoid)
template <int ACT, int ROUND>
__global__ void __launch_bounds__(256) gemm_tf32(
        const float* __restrict__ A, int lda, const float* __restrict__ B,
        const float* __restrict__ bias, const float* __restrict__ Cadd,
        float* __restrict__ C, int M, int N, int K) {
    __shared__ float As[3][BMT * BKT];
    __shared__ float Bs[3][BKT * BNT];
    int bz = blockIdx.z;
    A += (size_t)bz * K;                 // splitK: chunk offset along row
    B += (size_t)bz * K * N;
    C += (size_t)bz * M * N;

    int tid = threadIdx.x, lane = tid & 31, wid = tid >> 5;
    int wm = wid >> 2, wn = wid & 3;
    int g = lane >> 2, t4 = lane & 3;
    int bm = blockIdx.y * BMT, bn = blockIdx.x * BNT;

    int am = tid >> 2;
    int ak = (tid & 3) << 2;
    int bk = tid >> 5;
    int bn4 = (tid & 31) << 2;
    int a_dst0 = am * 16 + ((((ak >> 2) ^ (am >> 1)) & 3) << 2);
    int a_dst1 = (am + 64) * 16 + ((((ak >> 2) ^ ((am + 64) >> 1)) & 3) << 2);
    int b_dst0 = bk * 128 + (bn4 ^ (bk << 3));
    int b_dst1 = (bk + 8) * 128 + (bn4 ^ ((bk + 8) << 3));
    bool bpred = (bn + bn4) < N;
    const float* Abase = A + (size_t)(bm + am) * lda + ak;
    const float* Bbase = B + (size_t)bk * N + bn + bn4;

    float acc[4][4][4];
#pragma unroll
    for (int i = 0; i < 4; i++)
#pragma unroll
        for (int j = 0; j < 4; j++)
#pragma unroll
            for (int r = 0; r < 4; r++) acc[i][j][r] = 0.f;

    int KT = K / BKT;
#pragma unroll
    for (int s = 0; s < 3; s++) {
        int k0 = s * BKT;
        cp16(smem_u32(&As[s][a_dst0]), Abase + k0, true);
        cp16(smem_u32(&As[s][a_dst1]), Abase + (size_t)64 * lda + k0, true);
        cp16(smem_u32(&Bs[s][b_dst0]), Bbase + (size_t)k0 * N, bpred);
        cp16(smem_u32(&Bs[s][b_dst1]), Bbase + (size_t)(k0 + 8) * N, bpred);
        cp_commit();
    }

    for (int kt = 0; kt < KT; kt++) {
        cp_wait2();
        __syncthreads();
        int st = kt % 3;
        const float* as = As[st];
        const float* bs = Bs[st];
#pragma unroll
        for (int ks = 0; ks < BKT; ks += 8) {
            uint32_t af[4][4], bf[4][2];
#pragma unroll
            for (int i = 0; i < 4; i++) {
                int m0 = wm * 64 + 16 * i + g;
                int ro = m0 * 16 + t4;
                int sw = (m0 >> 1) & 3;
                int c0 = (((ks >> 2) + 0) ^ sw) << 2;
                int c1 = (((ks >> 2) + 1) ^ sw) << 2;
                af[i][0] = __float_as_uint(as[ro + c0]);
                af[i][1] = __float_as_uint(as[ro + 128 + c0]);
                af[i][2] = __float_as_uint(as[ro + c1]);
                af[i][3] = __float_as_uint(as[ro + 128 + c1]);
            }
#pragma unroll
            for (int j = 0; j < 4; j++) {
                int n0 = wn * 32 + 8 * j + g;
                int k0 = ks + t4, k1 = ks + t4 + 4;
                bf[j][0] = __float_as_uint(tf32r(bs[k0 * 128 + (n0 ^ (k0 << 3))]));
                bf[j][1] = __float_as_uint(tf32r(bs[k1 * 128 + (n0 ^ (k1 << 3))]));
            }
#pragma unroll
            for (int i = 0; i < 4; i++)
#pragma unroll
                for (int j = 0; j < 4; j++)
                    mma_tf32(acc[i][j], af[i], bf[j]);
        }
        __syncthreads();
        int kn = kt + 3;
        if (kn < KT) {
            int k0 = kn * BKT;
            cp16(smem_u32(&As[st][a_dst0]), Abase + k0, true);
            cp16(smem_u32(&As[st][a_dst1]), Abase + (size_t)64 * lda + k0, true);
            cp16(smem_u32(&Bs[st][b_dst0]), Bbase + (size_t)k0 * N, bpred);
            cp16(smem_u32(&Bs[st][b_dst1]), Bbase + (size_t)(k0 + 8) * N, bpred);
        }
        cp_commit();
    }

#pragma unroll
    for (int i = 0; i < 4; i++) {
        int r0 = bm + wm * 64 + 16 * i + g;
#pragma unroll
        for (int rr = 0; rr < 2; rr++) {
            int row = r0 + rr * 8;
#pragma unroll
            for (int j = 0; j < 4; j++) {
                int col = bn + wn * 32 + 8 * j + 2 * t4;
                if (col < N) {
                    float v0 = acc[i][j][rr * 2 + 0];
                    float v1 = acc[i][j][rr * 2 + 1];
                    if (bias) { v0 += bias[col]; v1 += bias[col + 1]; }
                    if (ACT == 1) { v0 = tanhf(v0); v1 = tanhf(v1); }
                    else if (ACT == 2) {
                        v0 = 1.f / (1.f + expf(-v0));
                        v1 = 1.f / (1.f + expf(-v1));
                    } else if (ACT == 3) {
                        v0 = expf(-0.606531f / (1.f + expf(-v0)));
                        v1 = expf(-0.606531f / (1.f + expf(-v1)));
                    }
                    if (Cadd) {
                        v0 += Cadd[(size_t)row * N + col];
                        v1 += Cadd[(size_t)row * N + col + 1];
                    }
                    if (ROUND) { v0 = tf32r(v0); v1 = tf32r(v1); }
                    *(float2*)&C[(size_t)row * N + col] = make_float2(v0, v1);
                }
            }
        }
    }
}

// ---------------- combine splitK partials + act + round ----------------
__global__ void combine_kernel(float* __restrict__ wpre, float* __restrict__ apre,
                               float* __restrict__ vpre, float* __restrict__ gpre) {
    int t = blockIdx.x;
    for (int idx = threadIdx.x; idx < 512; idx += 256) {
        int gi, n, N, off;
        if (idx < 96)       { gi = 0; n = idx;       N = 96;  off = PW; }
        else if (idx < 192) { gi = 1; n = idx - 96;  N = 96;  off = PA; }
        else if (idx < 256) { gi = 2; n = idx - 192; N = 64;  off = PV; }
        else                { gi = 3; n = idx - 256; N = 256; off = PG; }
        float s = 0.f;
#pragma unroll
        for (int kz = 0; kz < 4; kz++)
            s += g_part[off + ((size_t)kz * TT + t) * N + n];
        float r;
        if (gi == 0) r = tf32r(tanhf(s));
        else if (gi == 3) r = tf32r(1.f / (1.f + expf(-s)));
        else r = tf32r(s);
        if (gi == 0) wpre[t * 96 + n] = r;
        else if (gi == 1) apre[t * 96 + n] = r;
        else if (gi == 2) vpre[t * 64 + n] = r;
        else gpre[t * 256 + n] = r;
    }
}

// ---------------- K5: per-head prep (warp per (t,h)) ----------------
__global__ void prep_kernel(float* __restrict__ k, const float* __restrict__ a,
                            float* __restrict__ v, const float* __restrict__ v_first,
                            const float* __restrict__ vmix,
                            const float* __restrict__ k_k, const float* __restrict__ k_a,
                            float* __restrict__ kk, float* __restrict__ kka) {
    int hb = blockIdx.x * 8 + (threadIdx.x >> 5);
    int t = hb >> 5, h = hb & 31;
    int l = threadIdx.x & 31;
    int base = t * HID + h * HEAD;
    int hb0 = h * HEAD + l, hb1 = h * HEAD + l + 32;
    float k0 = k[base + l], k1 = k[base + 32 + l];
    float q0 = k0 * k_k[hb0], q1 = k1 * k_k[hb1];
    float ss = warp_sum(q0 * q0 + q1 * q1);
    float inv = 1.f / fmaxf(sqrtf(ss), 1e-12f);
    q0 *= inv; q1 *= inv;
    kk[base + l] = q0; kk[base + 32 + l] = q1;
    float a0 = a[base + l], a1 = a[base + 32 + l];
    kka[base + l] = q0 * a0; kka[base + 32 + l] = q1 * a1;
    k[base + l]      = k0 * (1.f + (a0 - 1.f) * k_a[hb0]);
    k[base + 32 + l] = k1 * (1.f + (a1 - 1.f) * k_a[hb1]);
    float v0 = v[base + l], v1 = v[base + 32 + l];
    v[base + l]      = v0 + (v_first[base + l]      - v0) * vmix[base + l];
    v[base + 32 + l] = v1 + (v_first[base + 32 + l] - v1) * vmix[base + 32 + l];
}

// ---------------- K6: sequential recurrence (f32x2, 1 barrier/step) ----
__device__ __forceinline__ float rec_load(int idx, int gb,
        const float* __restrict__ wv, const float* __restrict__ kkv,
        const float* __restrict__ kkav, const float* __restrict__ kv,
        const float* __restrict__ vv, const float* __restrict__ rv) {
    int arr = idx >> 6, j = idx & 63;
    const float* p;
    switch (arr) {
        case 0: p = wv; break;
        case 1: p = kkv; break;
        case 2: p = kkav; break;
        case 3: p = kv; break;
        case 4: p = vv; break;
        default: p = rv; break;
    }
    return p[gb + j];
}

__global__ void __launch_bounds__(256) recur_kernel(
        const float* __restrict__ S0,
        const float* __restrict__ wv, const float* __restrict__ kkv,
        const float* __restrict__ kkav, const float* __restrict__ kv,
        const float* __restrict__ vv, const float* __restrict__ rv,
        float* __restrict__ yout, float* __restrict__ S_out) {
    __shared__ __align__(16) float sh[2][384];
    int h = blockIdx.x;
    int tid = threadIdx.x;
    int row = tid >> 2;
    int q = tid & 3;
    int cb = q * 16;
    u64 s2[8];
    {
        const u64* sp = (const u64*)(S0 + h * 4096 + row * 64 + cb);
#pragma unroll
        for (int i = 0; i < 8; i++) s2[i] = sp[i];
    }
    int base0 = h * HEAD;
    bool lo = (tid < 128);
    // depth-2 prefetch
    float cur0 = rec_load(tid, base0, wv, kkv, kkav, kv, vv, rv);
    float cur1 = lo ? rec_load(tid + 256, base0, wv, kkv, kkav, kv, vv, rv) : 0.f;
    float nxt0 = rec_load(tid, HID + base0, wv, kkv, kkav, kv, vv, rv);
    float nxt1 = lo ? rec_load(tid + 256, HID + base0, wv, kkv, kkav, kv, vv, rv) : 0.f;

    for (int t = 0; t < TT; t++) {
        float* b = sh[t & 1];
        b[tid] = cur0;
        if (lo) b[tid + 256] = cur1;
        __syncthreads();
        float f0 = 0.f, f1 = 0.f;
        if (t + 2 < TT) {
            int gb = (t + 2) * HID + base0;
            f0 = rec_load(tid, gb, wv, kkv, kkav, kv, vv, rv);
            if (lo) f1 = rec_load(tid + 256, gb, wv, kkv, kkav, kv, vv, rv);
        }
        const u64* w2v = (const u64*)(b + cb);
        const u64* kk2 = (const u64*)(b + 64 + cb);
        const u64* a2v = (const u64*)(b + 128 + cb);
        const u64* k2v = (const u64*)(b + 192 + cb);
        const u64* r2v = (const u64*)(b + 320 + cb);
        // sab
        u64 sab2 = mul2(s2[0], kk2[0]);
#pragma unroll
        for (int i = 1; i < 8; i++) sab2 = fma2(s2[i], kk2[i], sab2);
        float2 su = unpk(sab2);
        float sab = su.x + su.y;
        sab += __shfl_xor_sync(0xffffffffu, sab, 1);
        sab += __shfl_xor_sync(0xffffffffu, sab, 2);
        u64 msab = dup2(-sab);
        u64 v2 = dup2(b[256 + row]);
        u64 y2 = 0;
        bool first = true;
#pragma unroll
        for (int i = 0; i < 8; i++) {
            u64 tmp = fma2(msab, a2v[i], mul2(v2, k2v[i]));
            s2[i] = fma2(s2[i], w2v[i], tmp);
            if (first) { y2 = mul2(s2[i], r2v[i]); first = false; }
            else y2 = fma2(s2[i], r2v[i], y2);
        }
        float2 yu = unpk(y2);
        float yy = yu.x + yu.y;
        yy += __shfl_xor_sync(0xffffffffu, yy, 1);
        yy += __shfl_xor_sync(0xffffffffu, yy, 2);
        if (q == 0) yout[t * HID + base0 + row] = yy;
        cur0 = nxt0; cur1 = nxt1; nxt0 = f0; nxt1 = f1;
    }
    u64* so = (u64*)(S_out + h * 4096 + row * 64 + cb);
#pragma unroll
    for (int i = 0; i < 8; i++) so[i] = s2[i];
}

// ---------------- K7: per-head LN + rkv + gate (warp per (t,h)) ---------
__global__ void post_kernel(const float* __restrict__ y, const float* __restrict__ r,
                            const float* __restrict__ k, const float* __restrict__ v,
                            const float* __restrict__ g, const float* __restrict__ r_k,
                            const float* __restrict__ lnw, const float* __restrict__ lnb,
                            float* __restrict__ z) {
    int hb = blockIdx.x * 8 + (threadIdx.x >> 5);
    int t = hb >> 5, h = hb & 31;
    int l = threadIdx.x & 31;
    int base = t * HID + h * HEAD;
    int hb0 = h * HEAD + l, hb1 = h * HEAD + l + 32;
    float y0 = y[base + l], y1 = y[base + 32 + l];
    float mu = warp_sum(y0 + y1) * (1.f / HEAD);
    float d0 = y0 - mu, d1 = y1 - mu;
    float var = warp_sum(d0 * d0 + d1 * d1) * (1.f / HEAD);
    float rs = rsqrtf(var + 0.00064f);
    float yn0 = d0 * rs * lnw[hb0] + lnb[hb0];
    float yn1 = d1 * rs * lnw[hb1] + lnb[hb1];
    float dot = warp_sum(r[base + l] * k[base + l] * r_k[hb0] +
                         r[base + 32 + l] * k[base + 32 + l] * r_k[hb1]);
    z[base + l]      = tf32r((yn0 + dot * v[base + l])      * g[base + l]);
    z[base + 32 + l] = tf32r((yn1 + dot * v[base + 32 + l]) * g[base + 32 + l]);
}

// ---------------- copy (v_first passthrough) ----------------
__global__ void copy4_kernel(const float4* __restrict__ src, float4* __restrict__ dst, int n4) {
    int i = blockIdx.x * blockDim.x + threadIdx.x;
    if (i < n4) dst[i] = src[i];
}

// ---------------- launch ----------------
extern "C" void kernel_launch(void* const* d_in, const int* in_sizes, int n_in,
                              void* d_out, int out_size) {
    const float* x       = (const float*)d_in[0];
    const float* state1  = (const float*)d_in[1];
    const float* state2  = (const float*)d_in[2];
    const float* v_first = (const float*)d_in[3];
    const float* ln1_w   = (const float*)d_in[4];
    const float* ln1_b   = (const float*)d_in[5];
    const float* x_r     = (const float*)d_in[6];
    const float* x_w     = (const float*)d_in[7];
    const float* x_k     = (const float*)d_in[8];
    const float* x_v     = (const float*)d_in[9];
    const float* x_a     = (const float*)d_in[10];
    const float* x_g     = (const float*)d_in[11];
    const float* Wr      = (const float*)d_in[12];
    const float* Wk      = (const float*)d_in[13];
    const float* Wv      = (const float*)d_in[14];
    const float* Wo      = (const float*)d_in[15];
    const float* w0      = (const float*)d_in[16];
    const float* w1      = (const float*)d_in[17];
    const float* w2      = (const float*)d_in[18];
    const float* a0      = (const float*)d_in[19];
    const float* a1      = (const float*)d_in[20];
    const float* a2      = (const float*)d_in[21];
    const float* v0      = (const float*)d_in[22];
    const float* v1      = (const float*)d_in[23];
    const float* v2      = (const float*)d_in[24];
    const float* g1      = (const float*)d_in[25];
    const float* g2      = (const float*)d_in[26];
    const float* k_k     = (const float*)d_in[27];
    const float* k_a     = (const float*)d_in[28];
    const float* r_k     = (const float*)d_in[29];
    const float* ln_x_w  = (const float*)d_in[30];
    const float* ln_x_b  = (const float*)d_in[31];

    float* out = (float*)d_out;
    float* out_main   = out;
    float* out_state1 = out + 2097152;
    float* out_S      = out + 2097152 + 2048;
    float* out_vfirst = out + 2097152 + 2048 + 131072;

    float *p_mix, *p_part;
    float *p_r, *p_k, *p_v, *p_w, *p_a, *p_g, *p_vmix, *p_kk, *p_kka, *p_y, *p_z;
    float *p_wpre, *p_apre, *p_vpre, *p_gpre;
    cudaGetSymbolAddress((void**)&p_mix, g_mix);
    cudaGetSymbolAddress((void**)&p_part, g_part);
    cudaGetSymbolAddress((void**)&p_r, g_r);
    cudaGetSymbolAddress((void**)&p_k, g_k);
    cudaGetSymbolAddress((void**)&p_v, g_v);
    cudaGetSymbolAddress((void**)&p_w, g_w);
    cudaGetSymbolAddress((void**)&p_a, g_a);
    cudaGetSymbolAddress((void**)&p_g, g_g);
    cudaGetSymbolAddress((void**)&p_vmix, g_vmix);
    cudaGetSymbolAddress((void**)&p_kk, g_kk);
    cudaGetSymbolAddress((void**)&p_kka, g_kka);
    cudaGetSymbolAddress((void**)&p_y, g_y);
    cudaGetSymbolAddress((void**)&p_z, g_z);
    cudaGetSymbolAddress((void**)&p_wpre, g_wpre);
    cudaGetSymbolAddress((void**)&p_apre, g_apre);
    cudaGetSymbolAddress((void**)&p_vpre, g_vpre);
    cudaGetSymbolAddress((void**)&p_gpre, g_gpre);

    float* mixp[6];
    for (int i = 0; i < 6; i++) mixp[i] = p_mix + (size_t)i * TT * HID;

    // K1: LN + token shift
    ln_shift_kernel<<<TT, 256>>>(x, state1, ln1_w, ln1_b,
                                 x_r, x_w, x_k, x_v, x_a, x_g, out_state1);

    // stage-1 skinny GEMMs with splitK (KZ=4, chunk 512)
    gemm_tf32<0,0><<<dim3(1, 8, 4), 256>>>(mixp[1], HID, w1, nullptr, nullptr, p_part + PW, TT, 96, 512);
    gemm_tf32<0,0><<<dim3(1, 8, 4), 256>>>(mixp[4], HID, a1, nullptr, nullptr, p_part + PA, TT, 96, 512);
    gemm_tf32<0,0><<<dim3(1, 8, 4), 256>>>(mixp[3], HID, v1, nullptr, nullptr, p_part + PV, TT, 64, 512);
    gemm_tf32<0,0><<<dim3(2, 8, 4), 256>>>(mixp[5], HID, g1, nullptr, nullptr, p_part + PG, TT, 256, 512);

    // big projections
    dim3 gBig(16, 8, 1);
    gemm_tf32<0,0><<<gBig, 256>>>(mixp[0], HID, Wr, nullptr, nullptr, p_r, TT, HID, HID);
    gemm_tf32<0,0><<<gBig, 256>>>(mixp[2], HID, Wk, nullptr, nullptr, p_k, TT, HID, HID);
    gemm_tf32<0,0><<<gBig, 256>>>(mixp[3], HID, Wv, nullptr, nullptr, p_v, TT, HID, HID);

    // combine stage-1 partials (act + round)
    combine_kernel<<<TT, 256>>>(p_wpre, p_apre, p_vpre, p_gpre);

    // stage-2
    gemm_tf32<3,0><<<gBig, 256>>>(p_wpre, 96,  w2, w0, nullptr, p_w,    TT, HID, 96);
    gemm_tf32<2,0><<<gBig, 256>>>(p_apre, 96,  a2, a0, nullptr, p_a,    TT, HID, 96);
    gemm_tf32<2,0><<<gBig, 256>>>(p_vpre, 64,  v2, v0, nullptr, p_vmix, TT, HID, 64);
    gemm_tf32<0,0><<<gBig, 256>>>(p_gpre, 256, g2, nullptr, nullptr, p_g, TT, HID, 256);

    // prep, recurrence, post
    prep_kernel<<<TT * NH / 8, 256>>>(p_k, p_a, p_v, v_first, p_vmix, k_k, k_a, p_kk, p_kka);
    recur_kernel<<<NH, 256>>>(state2, p_w, p_kk, p_kka, p_k, p_v, p_r, p_y, out_S);
    post_kernel<<<TT * NH / 8, 256>>>(p_y, p_r, p_k, p_v, p_g, r_k, ln_x_w, ln_x_b, p_z);

    // out = x + z @ Wo
    gemm_tf32<0,0><<<gBig, 256>>>(p_z, HID, Wo, nullptr, x, out_main, TT, HID, HID);

    // v_first passthrough
    copy4_kernel<<<(524288 + 255) / 256, 256>>>((const float4*)v_first, (float4*)out_vfirst, 524288);

    (void)in_sizes; (void)n_in; (void)out_size;
}

// round 10
// speedup vs baseline: 2.9265x; 1.1197x over previous
#include <cuda_runtime.h>
#include <math.h>
#include <stdint.h>

#define HID 2048
#define TT 1024
#define NH 32
#define HEAD 64

// ---------------- scratch ----------------
__device__ float g_mix[6][TT*HID];
__device__ float g_part[2097152];
__device__ float g_r   [TT*HID];
__device__ float g_k   [TT*HID];
__device__ float g_v   [TT*HID];
__device__ float g_w   [TT*HID];
__device__ float g_a   [TT*HID];
__device__ float g_g   [TT*HID];
__device__ float g_vmix[TT*HID];
__device__ float g_kk  [TT*HID];
__device__ float g_kka [TT*HID];
__device__ float g_y   [TT*HID];
__device__ float g_z   [TT*HID];
__device__ float g_wpre[TT*96];
__device__ float g_apre[TT*96];
__device__ float g_vpre[TT*64];
__device__ float g_gpre[TT*256];

#define PW 0
#define PA 393216
#define PV 786432
#define PG 1048576

// ---------------- helpers ----------------
typedef unsigned long long u64;
__device__ __forceinline__ float tf32r(float x) {
    float y;
    asm("cvt.rna.tf32.f32 %0, %1;" : "=f"(y) : "f"(x));
    return y;
}
__device__ __forceinline__ u64 fma2(u64 a, u64 b, u64 c) {
    u64 d; asm("fma.rn.f32x2 %0,%1,%2,%3;" : "=l"(d) : "l"(a), "l"(b), "l"(c)); return d;
}
__device__ __forceinline__ u64 mul2(u64 a, u64 b) {
    u64 d; asm("mul.rn.f32x2 %0,%1,%2;" : "=l"(d) : "l"(a), "l"(b)); return d;
}
__device__ __forceinline__ u64 add2(u64 a, u64 b) {
    u64 d; asm("add.rn.f32x2 %0,%1,%2;" : "=l"(d) : "l"(a), "l"(b)); return d;
}
__device__ __forceinline__ u64 dup2(float x) {
    u64 d; asm("mov.b64 %0,{%1,%1};" : "=l"(d) : "f"(x)); return d;
}
__device__ __forceinline__ float2 unpk(u64 a) {
    float lo, hi; asm("mov.b64 {%0,%1},%2;" : "=f"(lo), "=f"(hi) : "l"(a));
    return make_float2(lo, hi);
}
__device__ __forceinline__ float warp_sum(float v) {
#pragma unroll
    for (int o = 16; o; o >>= 1) v += __shfl_xor_sync(0xffffffffu, v, o);
    return v;
}
__device__ __forceinline__ void block_sum2(float& a, float& b, float* sbuf) {
#pragma unroll
    for (int o = 16; o; o >>= 1) {
        a += __shfl_xor_sync(0xffffffffu, a, o);
        b += __shfl_xor_sync(0xffffffffu, b, o);
    }
    int w = threadIdx.x >> 5, l = threadIdx.x & 31;
    int nw = blockDim.x >> 5;
    if (l == 0) { sbuf[w] = a; sbuf[32 + w] = b; }
    __syncthreads();
    if (threadIdx.x < 32) {
        float aa = (l < nw) ? sbuf[l] : 0.f;
        float bb = (l < nw) ? sbuf[32 + l] : 0.f;
#pragma unroll
        for (int o = 16; o; o >>= 1) {
            aa += __shfl_xor_sync(0xffffffffu, aa, o);
            bb += __shfl_xor_sync(0xffffffffu, bb, o);
        }
        if (l == 0) { sbuf[0] = aa; sbuf[32] = bb; }
    }
    __syncthreads();
    a = sbuf[0]; b = sbuf[32];
    __syncthreads();
}

// ---------------- K1: LayerNorm + token shift -> 6 rounded mixes --------
__global__ void ln_shift_kernel(const float* __restrict__ x,
                                const float* __restrict__ state1,
                                const float* __restrict__ lnw,
                                const float* __restrict__ lnb,
                                const float* __restrict__ c_r, const float* __restrict__ c_w,
                                const float* __restrict__ c_k, const float* __restrict__ c_v,
                                const float* __restrict__ c_a, const float* __restrict__ c_g,
                                float* __restrict__ state1_out) {
    __shared__ float sbuf[64];
    int t = blockIdx.x;
    int tid = threadIdx.x;
    float cur[8], prv[8];
    float s = 0.f, s2 = 0.f, ps = 0.f, ps2 = 0.f;
    const float* xr = x + (size_t)t * HID;
#pragma unroll
    for (int i = 0; i < 8; i++) {
        int j = tid + i * 256;
        float v = xr[j]; cur[i] = v; s += v; s2 += v * v;
    }
    if (t > 0) {
        const float* xp = x + (size_t)(t - 1) * HID;
#pragma unroll
        for (int i = 0; i < 8; i++) {
            int j = tid + i * 256;
            float v = xp[j]; prv[i] = v; ps += v; ps2 += v * v;
        }
    }
    block_sum2(s, s2, sbuf);
    float mu = s * (1.f / HID);
    float var = s2 * (1.f / HID) - mu * mu;
    float rs = rsqrtf(var + 1e-5f);
    float pmu = 0.f, prs = 0.f;
    if (t > 0) {
        block_sum2(ps, ps2, sbuf);
        pmu = ps * (1.f / HID);
        float pv = ps2 * (1.f / HID) - pmu * pmu;
        prs = rsqrtf(pv + 1e-5f);
    }
#pragma unroll
    for (int i = 0; i < 8; i++) {
        int j = tid + i * 256;
        float c = (cur[i] - mu) * rs * lnw[j] + lnb[j];
        float p = (t > 0) ? ((prv[i] - pmu) * prs * lnw[j] + lnb[j]) : state1[j];
        float sx = p - c;
        size_t o = (size_t)t * HID + j;
        g_mix[0][o] = tf32r(c + c_r[j] * sx);
        g_mix[1][o] = tf32r(c + c_w[j] * sx);
        g_mix[2][o] = tf32r(c + c_k[j] * sx);
        g_mix[3][o] = tf32r(c + c_v[j] * sx);
        g_mix[4][o] = tf32r(c + c_a[j] * sx);
        g_mix[5][o] = tf32r(c + c_g[j] * sx);
        if (t == TT - 1) state1_out[j] = c;
    }
}

// ---------------- tf32 tensor-core GEMM core ----------------
#define BMT 128
#define BNT 128
#define BKT 16

struct GSmem { float As[3][BMT * BKT]; float Bs[3][BKT * BNT]; };

__device__ __forceinline__ uint32_t smem_u32(const void* p) {
    return (uint32_t)__cvta_generic_to_shared(p);
}
__device__ __forceinline__ void cp16(uint32_t d, const float* s, bool pred) {
    int sz = pred ? 16 : 0;
    asm volatile("cp.async.cg.shared.global [%0], [%1], 16, %2;\n"
                 :: "r"(d), "l"(s), "r"(sz));
}
__device__ __forceinline__ void cp_commit() { asm volatile("cp.async.commit_group;\n" ::: "memory"); }
__device__ __forceinline__ void cp_wait2()  { asm volatile("cp.async.wait_group 2;\n" ::: "memory"); }

__device__ __forceinline__ void mma_tf32(float* c, const uint32_t* a, const uint32_t* b) {
    asm volatile("mma.sync.aligned.m16n8k8.row.col.f32.tf32.tf32.f32 "
                 "{%0,%1,%2,%3}, {%4,%5,%6,%7}, {%8,%9}, {%0,%1,%2,%3};"
                 : "+f"(c[0]), "+f"(c[1]), "+f"(c[2]), "+f"(c[3])
                 : "r"(a[0]), "r"(a[1]), "r"(a[2]), "r"(a[3]), "r"(b[0]), "r"(b[1]));
}

// act: 0 none, 1 tanh, 2 sigmoid, 3 decay exp(-0.606531*sigmoid)
__device__ __forceinline__ void gemm_core(
        GSmem& sm, const float* A, int lda, const float* B,
        const float* bias, const float* Cadd, float* C,
        int N, int K, int act, int rnd, int bm, int bn) {
    int tid = threadIdx.x, lane = tid & 31, wid = tid >> 5;
    int wm = wid >> 2, wn = wid & 3;
    int g = lane >> 2, t4 = lane & 3;

    int am = tid >> 2;
    int ak = (tid & 3) << 2;
    int bk = tid >> 5;
    int bn4 = (tid & 31) << 2;
    int a_dst0 = am * 16 + ((((ak >> 2) ^ (am >> 1)) & 3) << 2);
    int a_dst1 = (am + 64) * 16 + ((((ak >> 2) ^ ((am + 64) >> 1)) & 3) << 2);
    int b_dst0 = bk * 128 + (bn4 ^ (bk << 3));
    int b_dst1 = (bk + 8) * 128 + (bn4 ^ ((bk + 8) << 3));
    bool bpred = (bn + bn4) < N;
    const float* Abase = A + (size_t)(bm + am) * lda + ak;
    const float* Bbase = B + (size_t)bk * N + bn + bn4;

    float acc[4][4][4];
#pragma unroll
    for (int i = 0; i < 4; i++)
#pragma unroll
        for (int j = 0; j < 4; j++)
#pragma unroll
            for (int r = 0; r < 4; r++) acc[i][j][r] = 0.f;

    int KT = K / BKT;
#pragma unroll
    for (int s = 0; s < 3; s++) {
        int k0 = s * BKT;
        cp16(smem_u32(&sm.As[s][a_dst0]), Abase + k0, true);
        cp16(smem_u32(&sm.As[s][a_dst1]), Abase + (size_t)64 * lda + k0, true);
        cp16(smem_u32(&sm.Bs[s][b_dst0]), Bbase + (size_t)k0 * N, bpred);
        cp16(smem_u32(&sm.Bs[s][b_dst1]), Bbase + (size_t)(k0 + 8) * N, bpred);
        cp_commit();
    }

    for (int kt = 0; kt < KT; kt++) {
        cp_wait2();
        __syncthreads();
        int st = kt % 3;
        const float* as = sm.As[st];
        const float* bs = sm.Bs[st];
#pragma unroll
        for (int ks = 0; ks < BKT; ks += 8) {
            uint32_t af[4][4], bf[4][2];
#pragma unroll
            for (int i = 0; i < 4; i++) {
                int m0 = wm * 64 + 16 * i + g;
                int ro = m0 * 16 + t4;
                int sw = (m0 >> 1) & 3;
                int c0 = (((ks >> 2) + 0) ^ sw) << 2;
                int c1 = (((ks >> 2) + 1) ^ sw) << 2;
                af[i][0] = __float_as_uint(as[ro + c0]);
                af[i][1] = __float_as_uint(as[ro + 128 + c0]);
                af[i][2] = __float_as_uint(as[ro + c1]);
                af[i][3] = __float_as_uint(as[ro + 128 + c1]);
            }
#pragma unroll
            for (int j = 0; j < 4; j++) {
                int n0 = wn * 32 + 8 * j + g;
                int k0 = ks + t4, k1 = ks + t4 + 4;
                bf[j][0] = __float_as_uint(tf32r(bs[k0 * 128 + (n0 ^ (k0 << 3))]));
                bf[j][1] = __float_as_uint(tf32r(bs[k1 * 128 + (n0 ^ (k1 << 3))]));
            }
#pragma unroll
            for (int i = 0; i < 4; i++)
#pragma unroll
                for (int j = 0; j < 4; j++)
                    mma_tf32(acc[i][j], af[i], bf[j]);
        }
        __syncthreads();
        int kn = kt + 3;
        if (kn < KT) {
            int k0 = kn * BKT;
            cp16(smem_u32(&sm.As[st][a_dst0]), Abase + k0, true);
            cp16(smem_u32(&sm.As[st][a_dst1]), Abase + (size_t)64 * lda + k0, true);
            cp16(smem_u32(&sm.Bs[st][b_dst0]), Bbase + (size_t)k0 * N, bpred);
            cp16(smem_u32(&sm.Bs[st][b_dst1]), Bbase + (size_t)(k0 + 8) * N, bpred);
        }
        cp_commit();
    }

#pragma unroll
    for (int i = 0; i < 4; i++) {
        int r0 = bm + wm * 64 + 16 * i + g;
#pragma unroll
        for (int rr = 0; rr < 2; rr++) {
            int row = r0 + rr * 8;
#pragma unroll
            for (int j = 0; j < 4; j++) {
                int col = bn + wn * 32 + 8 * j + 2 * t4;
                if (col < N) {
                    float v0 = acc[i][j][rr * 2 + 0];
                    float v1 = acc[i][j][rr * 2 + 1];
                    if (bias) { v0 += bias[col]; v1 += bias[col + 1]; }
                    if (act == 1) { v0 = tanhf(v0); v1 = tanhf(v1); }
                    else if (act == 2) {
                        v0 = 1.f / (1.f + expf(-v0));
                        v1 = 1.f / (1.f + expf(-v1));
                    } else if (act == 3) {
                        v0 = expf(-0.606531f / (1.f + expf(-v0)));
                        v1 = expf(-0.606531f / (1.f + expf(-v1)));
                    }
                    if (Cadd) {
                        v0 += Cadd[(size_t)row * N + col];
                        v1 += Cadd[(size_t)row * N + col + 1];
                    }
                    if (rnd) { v0 = tf32r(v0); v1 = tf32r(v1); }
                    *(float2*)&C[(size_t)row * N + col] = make_float2(v0, v1);
                }
            }
        }
    }
}

// ---------------- batched GEMM wrappers ----------------
struct Batch3 { const float* A[3]; const float* B[3]; const float* Cadd[3]; float* C[3]; };
struct BatchS1 { const float* A[4]; const float* B[4]; float* C[4]; int N[4]; };
struct BatchS2 { const float* A[4]; const float* B[4]; const float* bias[4]; float* C[4]; int K[4]; int act[4]; };

// projections / Wo: N=HID, K=HID, act 0
__global__ void __launch_bounds__(256, 2) gemm_proj(Batch3 bt) {
    __shared__ GSmem sm;
    int op = blockIdx.z;
    gemm_core(sm, bt.A[op], HID, bt.B[op], nullptr, bt.Cadd[op], bt.C[op],
              HID, HID, 0, 0, blockIdx.y * BMT, blockIdx.x * BNT);
}

// stage-1 splitK: 20 CTAs in x: ops {w,a,v: 1 xtile; g: 2 xtiles} x kz4
__global__ void __launch_bounds__(256, 2) gemm_s1(BatchS1 bt) {
    __shared__ GSmem sm;
    int bx = blockIdx.x;
    int op = (bx < 16) ? (bx >> 2) : 3;
    int xt = (bx < 16) ? 0 : 1;
    int kz = bx & 3;
    int N = bt.N[op];
    const float* A = bt.A[op] + kz * 512;
    const float* B = bt.B[op] + (size_t)kz * 512 * N;
    float* C = bt.C[op] + (size_t)kz * TT * N;
    gemm_core(sm, A, HID, B, nullptr, nullptr, C,
              N, 512, 0, 0, blockIdx.y * BMT, xt * BNT);
}

// stage-2: 64 CTAs in x: op = bx>>4, xtile = bx&15; N=HID
__global__ void __launch_bounds__(256, 2) gemm_s2(BatchS2 bt) {
    __shared__ GSmem sm;
    int bx = blockIdx.x;
    int op = bx >> 4;
    int xt = bx & 15;
    gemm_core(sm, bt.A[op], bt.K[op], bt.B[op], bt.bias[op], nullptr, bt.C[op],
              HID, bt.K[op], bt.act[op], 0, blockIdx.y * BMT, xt * BNT);
}

// ---------------- combine splitK partials + act + round ----------------
__global__ void combine_kernel(float* __restrict__ wpre, float* __restrict__ apre,
                               float* __restrict__ vpre, float* __restrict__ gpre) {
    int t = blockIdx.x;
    for (int idx = threadIdx.x; idx < 512; idx += 256) {
        int gi, n, N, off;
        if (idx < 96)       { gi = 0; n = idx;       N = 96;  off = PW; }
        else if (idx < 192) { gi = 1; n = idx - 96;  N = 96;  off = PA; }
        else if (idx < 256) { gi = 2; n = idx - 192; N = 64;  off = PV; }
        else                { gi = 3; n = idx - 256; N = 256; off = PG; }
        float s = 0.f;
#pragma unroll
        for (int kz = 0; kz < 4; kz++)
            s += g_part[off + ((size_t)kz * TT + t) * N + n];
        float r;
        if (gi == 0) r = tf32r(tanhf(s));
        else if (gi == 3) r = tf32r(1.f / (1.f + expf(-s)));
        else r = tf32r(s);
        if (gi == 0) wpre[t * 96 + n] = r;
        else if (gi == 1) apre[t * 96 + n] = r;
        else if (gi == 2) vpre[t * 64 + n] = r;
        else gpre[t * 256 + n] = r;
    }
}

// ---------------- K5: per-head prep (warp per (t,h)) ----------------
__global__ void prep_kernel(float* __restrict__ k, const float* __restrict__ a,
                            float* __restrict__ v, const float* __restrict__ v_first,
                            const float* __restrict__ vmix,
                            const float* __restrict__ k_k, const float* __restrict__ k_a,
                            float* __restrict__ kk, float* __restrict__ kka) {
    int hb = blockIdx.x * 8 + (threadIdx.x >> 5);
    int t = hb >> 5, h = hb & 31;
    int l = threadIdx.x & 31;
    int base = t * HID + h * HEAD;
    int hb0 = h * HEAD + l, hb1 = h * HEAD + l + 32;
    float k0 = k[base + l], k1 = k[base + 32 + l];
    float q0 = k0 * k_k[hb0], q1 = k1 * k_k[hb1];
    float ss = warp_sum(q0 * q0 + q1 * q1);
    float inv = 1.f / fmaxf(sqrtf(ss), 1e-12f);
    q0 *= inv; q1 *= inv;
    kk[base + l] = q0; kk[base + 32 + l] = q1;
    float a0 = a[base + l], a1 = a[base + 32 + l];
    kka[base + l] = q0 * a0; kka[base + 32 + l] = q1 * a1;
    k[base + l]      = k0 * (1.f + (a0 - 1.f) * k_a[hb0]);
    k[base + 32 + l] = k1 * (1.f + (a1 - 1.f) * k_a[hb1]);
    float v0 = v[base + l], v1 = v[base + 32 + l];
    v[base + l]      = v0 + (v_first[base + l]      - v0) * vmix[base + l];
    v[base + 32 + l] = v1 + (v_first[base + 32 + l] - v1) * vmix[base + 32 + l];
}

// ---------------- K6: recurrence, 2 steps per barrier ----------------
__device__ __forceinline__ float rec_load(int idx, int gb,
        const float* __restrict__ wv, const float* __restrict__ kkv,
        const float* __restrict__ kkav, const float* __restrict__ kv,
        const float* __restrict__ vv, const float* __restrict__ rv) {
    int arr = idx >> 6, j = idx & 63;
    const float* p;
    switch (arr) {
        case 0: p = wv; break;
        case 1: p = kkv; break;
        case 2: p = kkav; break;
        case 3: p = kv; break;
        case 4: p = vv; break;
        default: p = rv; break;
    }
    return p[gb + j];
}

__device__ __forceinline__ float rec_step(const float* __restrict__ b,
                                          u64* s2, int row, int cb) {
    const u64* w2v = (const u64*)(b + cb);
    const u64* kk2 = (const u64*)(b + 64 + cb);
    const u64* a2v = (const u64*)(b + 128 + cb);
    const u64* k2v = (const u64*)(b + 192 + cb);
    const u64* r2v = (const u64*)(b + 320 + cb);
    // sab dot, 2 parallel chains
    u64 sA = mul2(s2[0], kk2[0]);
    u64 sB = mul2(s2[1], kk2[1]);
#pragma unroll
    for (int i = 2; i < 8; i += 2) {
        sA = fma2(s2[i], kk2[i], sA);
        sB = fma2(s2[i + 1], kk2[i + 1], sB);
    }
    u64 sT = add2(sA, sB);
    float2 su = unpk(sT);
    float sab = su.x + su.y;
    sab += __shfl_xor_sync(0xffffffffu, sab, 1);
    sab += __shfl_xor_sync(0xffffffffu, sab, 2);
    u64 msab = dup2(-sab);
    u64 v2 = dup2(b[256 + row]);
    u64 yA = 0, yB = 0;
#pragma unroll
    for (int i = 0; i < 8; i += 2) {
        u64 t0 = fma2(msab, a2v[i], mul2(v2, k2v[i]));
        u64 t1 = fma2(msab, a2v[i + 1], mul2(v2, k2v[i + 1]));
        s2[i] = fma2(s2[i], w2v[i], t0);
        s2[i + 1] = fma2(s2[i + 1], w2v[i + 1], t1);
        if (i == 0) { yA = mul2(s2[0], r2v[0]); yB = mul2(s2[1], r2v[1]); }
        else { yA = fma2(s2[i], r2v[i], yA); yB = fma2(s2[i + 1], r2v[i + 1], yB); }
    }
    float2 yu = unpk(add2(yA, yB));
    float yy = yu.x + yu.y;
    yy += __shfl_xor_sync(0xffffffffu, yy, 1);
    yy += __shfl_xor_sync(0xffffffffu, yy, 2);
    return yy;
}

__global__ void __launch_bounds__(256) recur_kernel(
        const float* __restrict__ S0,
        const float* __restrict__ wv, const float* __restrict__ kkv,
        const float* __restrict__ kkav, const float* __restrict__ kv,
        const float* __restrict__ vv, const float* __restrict__ rv,
        float* __restrict__ yout, float* __restrict__ S_out) {
    __shared__ __align__(16) float sh[4][384];
    int h = blockIdx.x;
    int tid = threadIdx.x;
    int row = tid >> 2;
    int q = tid & 3;
    int cb = q * 16;
    u64 s2[8];
    {
        const u64* sp = (const u64*)(S0 + h * 4096 + row * 64 + cb);
#pragma unroll
        for (int i = 0; i < 8; i++) s2[i] = sp[i];
    }
    int base0 = h * HEAD;
    bool lo = (tid < 128);
    // load steps 0 and 1
    float c00 = rec_load(tid, base0, wv, kkv, kkav, kv, vv, rv);
    float c01 = lo ? rec_load(tid + 256, base0, wv, kkv, kkav, kv, vv, rv) : 0.f;
    float c10 = rec_load(tid, HID + base0, wv, kkv, kkav, kv, vv, rv);
    float c11 = lo ? rec_load(tid + 256, HID + base0, wv, kkv, kkav, kv, vv, rv) : 0.f;

    for (int it = 0; it < TT / 2; it++) {
        int t = it * 2;
        float* b0 = sh[(it & 1) * 2 + 0];
        float* b1 = sh[(it & 1) * 2 + 1];
        b0[tid] = c00; if (lo) b0[tid + 256] = c01;
        b1[tid] = c10; if (lo) b1[tid + 256] = c11;
        __syncthreads();
        // prefetch steps t+2, t+3
        if (t + 2 < TT) {
            int gb = (t + 2) * HID + base0;
            c00 = rec_load(tid, gb, wv, kkv, kkav, kv, vv, rv);
            if (lo) c01 = rec_load(tid + 256, gb, wv, kkv, kkav, kv, vv, rv);
            gb += HID;
            c10 = rec_load(tid, gb, wv, kkv, kkav, kv, vv, rv);
            if (lo) c11 = rec_load(tid + 256, gb, wv, kkv, kkav, kv, vv, rv);
        }
        float y0 = rec_step(b0, s2, row, cb);
        if (q == 0) yout[t * HID + base0 + row] = y0;
        float y1 = rec_step(b1, s2, row, cb);
        if (q == 0) yout[(t + 1) * HID + base0 + row] = y1;
    }
    u64* so = (u64*)(S_out + h * 4096 + row * 64 + cb);
#pragma unroll
    for (int i = 0; i < 8; i++) so[i] = s2[i];
}

// ---------------- K7: per-head LN + rkv + gate ----------------
__global__ void post_kernel(const float* __restrict__ y, const float* __restrict__ r,
                            const float* __restrict__ k, const float* __restrict__ v,
                            const float* __restrict__ g, const float* __restrict__ r_k,
                            const float* __restrict__ lnw, const float* __restrict__ lnb,
                            float* __restrict__ z) {
    int hb = blockIdx.x * 8 + (threadIdx.x >> 5);
    int t = hb >> 5, h = hb & 31;
    int l = threadIdx.x & 31;
    int base = t * HID + h * HEAD;
    int hb0 = h * HEAD + l, hb1 = h * HEAD + l + 32;
    float y0 = y[base + l], y1 = y[base + 32 + l];
    float mu = warp_sum(y0 + y1) * (1.f / HEAD);
    float d0 = y0 - mu, d1 = y1 - mu;
    float var = warp_sum(d0 * d0 + d1 * d1) * (1.f / HEAD);
    float rs = rsqrtf(var + 0.00064f);
    float yn0 = d0 * rs * lnw[hb0] + lnb[hb0];
    float yn1 = d1 * rs * lnw[hb1] + lnb[hb1];
    float dot = warp_sum(r[base + l] * k[base + l] * r_k[hb0] +
                         r[base + 32 + l] * k[base + 32 + l] * r_k[hb1]);
    z[base + l]      = tf32r((yn0 + dot * v[base + l])      * g[base + l]);
    z[base + 32 + l] = tf32r((yn1 + dot * v[base + 32 + l]) * g[base + 32 + l]);
}

// ---------------- copy ----------------
__global__ void copy4_kernel(const float4* __restrict__ src, float4* __restrict__ dst, int n4) {
    int i = blockIdx.x * blockDim.x + threadIdx.x;
    if (i < n4) dst[i] = src[i];
}

// ---------------- launch ----------------
extern "C" void kernel_launch(void* const* d_in, const int* in_sizes, int n_in,
                              void* d_out, int out_size) {
    const float* x       = (const float*)d_in[0];
    const float* state1  = (const float*)d_in[1];
    const float* state2  = (const float*)d_in[2];
    const float* v_first = (const float*)d_in[3];
    const float* ln1_w   = (const float*)d_in[4];
    const float* ln1_b   = (const float*)d_in[5];
    const float* x_r     = (const float*)d_in[6];
    const float* x_w     = (const float*)d_in[7];
    const float* x_k     = (const float*)d_in[8];
    const float* x_v     = (const float*)d_in[9];
    const float* x_a     = (const float*)d_in[10];
    const float* x_g     = (const float*)d_in[11];
    const float* Wr      = (const float*)d_in[12];
    const float* Wk      = (const float*)d_in[13];
    const float* Wv      = (const float*)d_in[14];
    const float* Wo      = (const float*)d_in[15];
    const float* w0      = (const float*)d_in[16];
    const float* w1      = (const float*)d_in[17];
    const float* w2      = (const float*)d_in[18];
    const float* a0      = (const float*)d_in[19];
    const float* a1      = (const float*)d_in[20];
    const float* a2      = (const float*)d_in[21];
    const float* v0      = (const float*)d_in[22];
    const float* v1      = (const float*)d_in[23];
    const float* v2      = (const float*)d_in[24];
    const float* g1      = (const float*)d_in[25];
    const float* g2      = (const float*)d_in[26];
    const float* k_k     = (const float*)d_in[27];
    const float* k_a     = (const float*)d_in[28];
    const float* r_k     = (const float*)d_in[29];
    const float* ln_x_w  = (const float*)d_in[30];
    const float* ln_x_b  = (const float*)d_in[31];

    float* out = (float*)d_out;
    float* out_main   = out;
    float* out_state1 = out + 2097152;
    float* out_S      = out + 2097152 + 2048;
    float* out_vfirst = out + 2097152 + 2048 + 131072;

    float *p_mix, *p_part;
    float *p_r, *p_k, *p_v, *p_w, *p_a, *p_g, *p_vmix, *p_kk, *p_kka, *p_y, *p_z;
    float *p_wpre, *p_apre, *p_vpre, *p_gpre;
    cudaGetSymbolAddress((void**)&p_mix, g_mix);
    cudaGetSymbolAddress((void**)&p_part, g_part);
    cudaGetSymbolAddress((void**)&p_r, g_r);
    cudaGetSymbolAddress((void**)&p_k, g_k);
    cudaGetSymbolAddress((void**)&p_v, g_v);
    cudaGetSymbolAddress((void**)&p_w, g_w);
    cudaGetSymbolAddress((void**)&p_a, g_a);
    cudaGetSymbolAddress((void**)&p_g, g_g);
    cudaGetSymbolAddress((void**)&p_vmix, g_vmix);
    cudaGetSymbolAddress((void**)&p_kk, g_kk);
    cudaGetSymbolAddress((void**)&p_kka, g_kka);
    cudaGetSymbolAddress((void**)&p_y, g_y);
    cudaGetSymbolAddress((void**)&p_z, g_z);
    cudaGetSymbolAddress((void**)&p_wpre, g_wpre);
    cudaGetSymbolAddress((void**)&p_apre, g_apre);
    cudaGetSymbolAddress((void**)&p_vpre, g_vpre);
    cudaGetSymbolAddress((void**)&p_gpre, g_gpre);

    float* mixp[6];
    for (int i = 0; i < 6; i++) mixp[i] = p_mix + (size_t)i * TT * HID;

    // K1: LN + token shift
    ln_shift_kernel<<<TT, 256>>>(x, state1, ln1_w, ln1_b,
                                 x_r, x_w, x_k, x_v, x_a, x_g, out_state1);

    // stage-1 skinny, batched splitK (one launch, 160 CTAs)
    BatchS1 b1;
    b1.A[0] = mixp[1]; b1.B[0] = w1; b1.C[0] = p_part + PW; b1.N[0] = 96;
    b1.A[1] = mixp[4]; b1.B[1] = a1; b1.C[1] = p_part + PA; b1.N[1] = 96;
    b1.A[2] = mixp[3]; b1.B[2] = v1; b1.C[2] = p_part + PV; b1.N[2] = 64;
    b1.A[3] = mixp[5]; b1.B[3] = g1; b1.C[3] = p_part + PG; b1.N[3] = 256;
    gemm_s1<<<dim3(20, 8), 256>>>(b1);

    // big projections, batched (one launch, 384 CTAs)
    Batch3 bp;
    bp.A[0] = mixp[0]; bp.B[0] = Wr; bp.Cadd[0] = nullptr; bp.C[0] = p_r;
    bp.A[1] = mixp[2]; bp.B[1] = Wk; bp.Cadd[1] = nullptr; bp.C[1] = p_k;
    bp.A[2] = mixp[3]; bp.B[2] = Wv; bp.Cadd[2] = nullptr; bp.C[2] = p_v;
    gemm_proj<<<dim3(16, 8, 3), 256>>>(bp);

    // combine stage-1 partials
    combine_kernel<<<TT, 256>>>(p_wpre, p_apre, p_vpre, p_gpre);

    // stage-2, batched (one launch, 512 CTAs)
    BatchS2 b2;
    b2.A[0] = p_wpre; b2.B[0] = w2; b2.bias[0] = w0;      b2.C[0] = p_w;    b2.K[0] = 96;  b2.act[0] = 3;
    b2.A[1] = p_apre; b2.B[1] = a2; b2.bias[1] = a0;      b2.C[1] = p_a;    b2.K[1] = 96;  b2.act[1] = 2;
    b2.A[2] = p_vpre; b2.B[2] = v2; b2.bias[2] = v0;      b2.C[2] = p_vmix; b2.K[2] = 64;  b2.act[2] = 2;
    b2.A[3] = p_gpre; b2.B[3] = g2; b2.bias[3] = nullptr; b2.C[3] = p_g;    b2.K[3] = 256; b2.act[3] = 0;
    gemm_s2<<<dim3(64, 8), 256>>>(b2);

    // prep, recurrence, post
    prep_kernel<<<TT * NH / 8, 256>>>(p_k, p_a, p_v, v_first, p_vmix, k_k, k_a, p_kk, p_kka);
    recur_kernel<<<NH, 256>>>(state2, p_w, p_kk, p_kka, p_k, p_v, p_r, p_y, out_S);
    post_kernel<<<TT * NH / 8, 256>>>(p_y, p_r, p_k, p_v, p_g, r_k, ln_x_w, ln_x_b, p_z);

    // out = x + z @ Wo (single-op batch)
    Batch3 bo;
    bo.A[0] = p_z; bo.B[0] = Wo; bo.Cadd[0] = x; bo.C[0] = out_main;
    bo.A[1] = bo.A[0]; bo.B[1] = bo.B[0]; bo.Cadd[1] = nullptr; bo.C[1] = bo.C[0];
    bo.A[2] = bo.A[0]; bo.B[2] = bo.B[0]; bo.Cadd[2] = nullptr; bo.C[2] = bo.C[0];
    gemm_proj<<<dim3(16, 8, 1), 256>>>(bo);

    // v_first passthrough
    copy4_kernel<<<(524288 + 255) / 256, 256>>>((const float4*)v_first, (float4*)out_vfirst, 524288);

    (void)in_sizes; (void)n_in; (void)out_size;
}

// round 17
// speedup vs baseline: 3.1046x; 1.0609x over previous
#include <cuda_runtime.h>
#include <math.h>
#include <stdint.h>

#define HID 2048
#define TT 1024
#define NH 32
#define HEAD 64

// ---------------- scratch ----------------
__device__ float g_mix[6][TT*HID];
__device__ float g_part[2097152];
__device__ float g_r   [TT*HID];
__device__ float g_k   [TT*HID];
__device__ float g_v   [TT*HID];
__device__ float g_w   [TT*HID];
__device__ float g_a   [TT*HID];
__device__ float g_g   [TT*HID];
__device__ float g_vmix[TT*HID];
__device__ float g_kk  [TT*HID];
__device__ float g_kka [TT*HID];
__device__ float g_y   [TT*HID];
__device__ float g_z   [TT*HID];
__device__ float g_wpre[TT*96];
__device__ float g_apre[TT*96];
__device__ float g_vpre[TT*64];
__device__ float g_gpre[TT*256];

#define PW 0
#define PA 393216
#define PV 786432
#define PG 1048576

// ---------------- helpers ----------------
typedef unsigned long long u64;
__device__ __forceinline__ float tf32r(float x) {
    float y;
    asm("cvt.rna.tf32.f32 %0, %1;" : "=f"(y) : "f"(x));
    return y;
}
__device__ __forceinline__ u64 fma2(u64 a, u64 b, u64 c) {
    u64 d; asm("fma.rn.f32x2 %0,%1,%2,%3;" : "=l"(d) : "l"(a), "l"(b), "l"(c)); return d;
}
__device__ __forceinline__ u64 mul2(u64 a, u64 b) {
    u64 d; asm("mul.rn.f32x2 %0,%1,%2;" : "=l"(d) : "l"(a), "l"(b)); return d;
}
__device__ __forceinline__ u64 add2(u64 a, u64 b) {
    u64 d; asm("add.rn.f32x2 %0,%1,%2;" : "=l"(d) : "l"(a), "l"(b)); return d;
}
__device__ __forceinline__ u64 dup2(float x) {
    u64 d; asm("mov.b64 %0,{%1,%1};" : "=l"(d) : "f"(x)); return d;
}
__device__ __forceinline__ float2 unpk(u64 a) {
    float lo, hi; asm("mov.b64 {%0,%1},%2;" : "=f"(lo), "=f"(hi) : "l"(a));
    return make_float2(lo, hi);
}
__device__ __forceinline__ float warp_sum(float v) {
#pragma unroll
    for (int o = 16; o; o >>= 1) v += __shfl_xor_sync(0xffffffffu, v, o);
    return v;
}
__device__ __forceinline__ void block_sum2(float& a, float& b, float* sbuf) {
#pragma unroll
    for (int o = 16; o; o >>= 1) {
        a += __shfl_xor_sync(0xffffffffu, a, o);
        b += __shfl_xor_sync(0xffffffffu, b, o);
    }
    int w = threadIdx.x >> 5, l = threadIdx.x & 31;
    int nw = blockDim.x >> 5;
    if (l == 0) { sbuf[w] = a; sbuf[32 + w] = b; }
    __syncthreads();
    if (threadIdx.x < 32) {
        float aa = (l < nw) ? sbuf[l] : 0.f;
        float bb = (l < nw) ? sbuf[32 + l] : 0.f;
#pragma unroll
        for (int o = 16; o; o >>= 1) {
            aa += __shfl_xor_sync(0xffffffffu, aa, o);
            bb += __shfl_xor_sync(0xffffffffu, bb, o);
        }
        if (l == 0) { sbuf[0] = aa; sbuf[32] = bb; }
    }
    __syncthreads();
    a = sbuf[0]; b = sbuf[32];
    __syncthreads();
}

// ---------------- K1: LayerNorm + token shift -> 6 rounded mixes --------
__global__ void ln_shift_kernel(const float* __restrict__ x,
                                const float* __restrict__ state1,
                                const float* __restrict__ lnw,
                                const float* __restrict__ lnb,
                                const float* __restrict__ c_r, const float* __restrict__ c_w,
                                const float* __restrict__ c_k, const float* __restrict__ c_v,
                                const float* __restrict__ c_a, const float* __restrict__ c_g,
                                float* __restrict__ state1_out) {
    __shared__ float sbuf[64];
    int t = blockIdx.x;
    int tid = threadIdx.x;
    float cur[8], prv[8];
    float s = 0.f, s2 = 0.f, ps = 0.f, ps2 = 0.f;
    const float* xr = x + (size_t)t * HID;
#pragma unroll
    for (int i = 0; i < 8; i++) {
        int j = tid + i * 256;
        float v = xr[j]; cur[i] = v; s += v; s2 += v * v;
    }
    if (t > 0) {
        const float* xp = x + (size_t)(t - 1) * HID;
#pragma unroll
        for (int i = 0; i < 8; i++) {
            int j = tid + i * 256;
            float v = xp[j]; prv[i] = v; ps += v; ps2 += v * v;
        }
    }
    block_sum2(s, s2, sbuf);
    float mu = s * (1.f / HID);
    float var = s2 * (1.f / HID) - mu * mu;
    float rs = rsqrtf(var + 1e-5f);
    float pmu = 0.f, prs = 0.f;
    if (t > 0) {
        block_sum2(ps, ps2, sbuf);
        pmu = ps * (1.f / HID);
        float pv = ps2 * (1.f / HID) - pmu * pmu;
        prs = rsqrtf(pv + 1e-5f);
    }
#pragma unroll
    for (int i = 0; i < 8; i++) {
        int j = tid + i * 256;
        float c = (cur[i] - mu) * rs * lnw[j] + lnb[j];
        float p = (t > 0) ? ((prv[i] - pmu) * prs * lnw[j] + lnb[j]) : state1[j];
        float sx = p - c;
        size_t o = (size_t)t * HID + j;
        g_mix[0][o] = tf32r(c + c_r[j] * sx);
        g_mix[1][o] = tf32r(c + c_w[j] * sx);
        g_mix[2][o] = tf32r(c + c_k[j] * sx);
        g_mix[3][o] = tf32r(c + c_v[j] * sx);
        g_mix[4][o] = tf32r(c + c_a[j] * sx);
        g_mix[5][o] = tf32r(c + c_g[j] * sx);
        if (t == TT - 1) state1_out[j] = c;
    }
}

// ---------------- tf32 tensor-core GEMM core ----------------
#define BMT 128
#define BNT 128
#define BKT 16

struct GSmem { float As[3][BMT * BKT]; float Bs[3][BKT * BNT]; };

__device__ __forceinline__ uint32_t smem_u32(const void* p) {
    return (uint32_t)__cvta_generic_to_shared(p);
}
__device__ __forceinline__ void cp16(uint32_t d, const float* s, bool pred) {
    int sz = pred ? 16 : 0;
    asm volatile("cp.async.cg.shared.global [%0], [%1], 16, %2;\n"
                 :: "r"(d), "l"(s), "r"(sz));
}
__device__ __forceinline__ void cp_commit() { asm volatile("cp.async.commit_group;\n" ::: "memory"); }
__device__ __forceinline__ void cp_wait2()  { asm volatile("cp.async.wait_group 2;\n" ::: "memory"); }

__device__ __forceinline__ void mma_tf32(float* c, const uint32_t* a, const uint32_t* b) {
    asm volatile("mma.sync.aligned.m16n8k8.row.col.f32.tf32.tf32.f32 "
                 "{%0,%1,%2,%3}, {%4,%5,%6,%7}, {%8,%9}, {%0,%1,%2,%3};"
                 : "+f"(c[0]), "+f"(c[1]), "+f"(c[2]), "+f"(c[3])
                 : "r"(a[0]), "r"(a[1]), "r"(a[2]), "r"(a[3]), "r"(b[0]), "r"(b[1]));
}

// act: 0 none, 1 tanh, 2 sigmoid, 3 decay exp(-0.606531*sigmoid)
__device__ __forceinline__ void gemm_core(
        GSmem& sm, const float* A, int lda, const float* B,
        const float* bias, const float* Cadd, float* C,
        int N, int K, int act, int rnd, int bm, int bn) {
    int tid = threadIdx.x, lane = tid & 31, wid = tid >> 5;
    int wm = wid >> 2, wn = wid & 3;
    int g = lane >> 2, t4 = lane & 3;

    int am = tid >> 2;
    int ak = (tid & 3) << 2;
    int bk = tid >> 5;
    int bn4 = (tid & 31) << 2;
    int a_dst0 = am * 16 + ((((ak >> 2) ^ (am >> 1)) & 3) << 2);
    int a_dst1 = (am + 64) * 16 + ((((ak >> 2) ^ ((am + 64) >> 1)) & 3) << 2);
    int b_dst0 = bk * 128 + (bn4 ^ (bk << 3));
    int b_dst1 = (bk + 8) * 128 + (bn4 ^ ((bk + 8) << 3));
    bool bpred = (bn + bn4) < N;
    const float* Abase = A + (size_t)(bm + am) * lda + ak;
    const float* Bbase = B + (size_t)bk * N + bn + bn4;

    float acc[4][4][4];
#pragma unroll
    for (int i = 0; i < 4; i++)
#pragma unroll
        for (int j = 0; j < 4; j++)
#pragma unroll
            for (int r = 0; r < 4; r++) acc[i][j][r] = 0.f;

    int KT = K / BKT;
#pragma unroll
    for (int s = 0; s < 3; s++) {
        int k0 = s * BKT;
        cp16(smem_u32(&sm.As[s][a_dst0]), Abase + k0, true);
        cp16(smem_u32(&sm.As[s][a_dst1]), Abase + (size_t)64 * lda + k0, true);
        cp16(smem_u32(&sm.Bs[s][b_dst0]), Bbase + (size_t)k0 * N, bpred);
        cp16(smem_u32(&sm.Bs[s][b_dst1]), Bbase + (size_t)(k0 + 8) * N, bpred);
        cp_commit();
    }

    for (int kt = 0; kt < KT; kt++) {
        cp_wait2();
        __syncthreads();
        int st = kt % 3;
        const float* as = sm.As[st];
        const float* bs = sm.Bs[st];
#pragma unroll
        for (int ks = 0; ks < BKT; ks += 8) {
            uint32_t af[4][4], bf[4][2];
#pragma unroll
            for (int i = 0; i < 4; i++) {
                int m0 = wm * 64 + 16 * i + g;
                int ro = m0 * 16 + t4;
                int sw = (m0 >> 1) & 3;
                int c0 = (((ks >> 2) + 0) ^ sw) << 2;
                int c1 = (((ks >> 2) + 1) ^ sw) << 2;
                af[i][0] = __float_as_uint(as[ro + c0]);
                af[i][1] = __float_as_uint(as[ro + 128 + c0]);
                af[i][2] = __float_as_uint(as[ro + c1]);
                af[i][3] = __float_as_uint(as[ro + 128 + c1]);
            }
#pragma unroll
            for (int j = 0; j < 4; j++) {
                int n0 = wn * 32 + 8 * j + g;
                int k0 = ks + t4, k1 = ks + t4 + 4;
                bf[j][0] = __float_as_uint(tf32r(bs[k0 * 128 + (n0 ^ (k0 << 3))]));
                bf[j][1] = __float_as_uint(tf32r(bs[k1 * 128 + (n0 ^ (k1 << 3))]));
            }
#pragma unroll
            for (int i = 0; i < 4; i++)
#pragma unroll
                for (int j = 0; j < 4; j++)
                    mma_tf32(acc[i][j], af[i], bf[j]);
        }
        __syncthreads();
        int kn = kt + 3;
        if (kn < KT) {
            int k0 = kn * BKT;
            cp16(smem_u32(&sm.As[st][a_dst0]), Abase + k0, true);
            cp16(smem_u32(&sm.As[st][a_dst1]), Abase + (size_t)64 * lda + k0, true);
            cp16(smem_u32(&sm.Bs[st][b_dst0]), Bbase + (size_t)k0 * N, bpred);
            cp16(smem_u32(&sm.Bs[st][b_dst1]), Bbase + (size_t)(k0 + 8) * N, bpred);
        }
        cp_commit();
    }

#pragma unroll
    for (int i = 0; i < 4; i++) {
        int r0 = bm + wm * 64 + 16 * i + g;
#pragma unroll
        for (int rr = 0; rr < 2; rr++) {
            int row = r0 + rr * 8;
#pragma unroll
            for (int j = 0; j < 4; j++) {
                int col = bn + wn * 32 + 8 * j + 2 * t4;
                if (col < N) {
                    float v0 = acc[i][j][rr * 2 + 0];
                    float v1 = acc[i][j][rr * 2 + 1];
                    if (bias) { v0 += bias[col]; v1 += bias[col + 1]; }
                    if (act == 1) { v0 = tanhf(v0); v1 = tanhf(v1); }
                    else if (act == 2) {
                        v0 = 1.f / (1.f + expf(-v0));
                        v1 = 1.f / (1.f + expf(-v1));
                    } else if (act == 3) {
                        v0 = expf(-0.606531f / (1.f + expf(-v0)));
                        v1 = expf(-0.606531f / (1.f + expf(-v1)));
                    }
                    if (Cadd) {
                        v0 += Cadd[(size_t)row * N + col];
                        v1 += Cadd[(size_t)row * N + col + 1];
                    }
                    if (rnd) { v0 = tf32r(v0); v1 = tf32r(v1); }
                    *(float2*)&C[(size_t)row * N + col] = make_float2(v0, v1);
                }
            }
        }
    }
}

// ---------------- batched GEMM wrappers ----------------
struct Batch3 { const float* A[3]; const float* B[3]; const float* Cadd[3]; float* C[3]; };
struct BatchS2 { const float* A[4]; const float* B[4]; const float* bias[4]; float* C[4]; int K[4]; int act[4]; };
// merged stage-1 + projections: s1 fields [0..3], proj fields [4..6]
struct BatchM {
    const float* A[7]; const float* B[7]; float* C[7]; int N[7];
};

// merged launch: x in [0,68): bx<20 -> stage-1 splitK, bx>=20 -> projections
__global__ void __launch_bounds__(256, 2) gemm_merged(BatchM bt) {
    __shared__ GSmem sm;
    int bx = blockIdx.x;
    if (bx < 20) {
        int op = (bx < 16) ? (bx >> 2) : 3;
        int xt = (bx < 16) ? 0 : 1;
        int kz = bx & 3;
        int N = bt.N[op];
        const float* A = bt.A[op] + kz * 512;
        const float* B = bt.B[op] + (size_t)kz * 512 * N;
        float* C = bt.C[op] + (size_t)kz * TT * N;
        gemm_core(sm, A, HID, B, nullptr, nullptr, C,
                  N, 512, 0, 0, blockIdx.y * BMT, xt * BNT);
    } else {
        int pid = bx - 20;          // 0..47
        int op = 4 + (pid >> 4);    // 4..6
        int xt = pid & 15;
        gemm_core(sm, bt.A[op], HID, bt.B[op], nullptr, nullptr, bt.C[op],
                  HID, HID, 0, 0, blockIdx.y * BMT, xt * BNT);
    }
}

// projections / Wo: N=HID, K=HID, act 0
__global__ void __launch_bounds__(256, 2) gemm_proj(Batch3 bt) {
    __shared__ GSmem sm;
    int op = blockIdx.z;
    gemm_core(sm, bt.A[op], HID, bt.B[op], nullptr, bt.Cadd[op], bt.C[op],
              HID, HID, 0, 0, blockIdx.y * BMT, blockIdx.x * BNT);
}

// stage-2: 64 CTAs in x: op = bx>>4, xtile = bx&15; N=HID
__global__ void __launch_bounds__(256, 2) gemm_s2(BatchS2 bt) {
    __shared__ GSmem sm;
    int bx = blockIdx.x;
    int op = bx >> 4;
    int xt = bx & 15;
    gemm_core(sm, bt.A[op], bt.K[op], bt.B[op], bt.bias[op], nullptr, bt.C[op],
              HID, bt.K[op], bt.act[op], 0, blockIdx.y * BMT, xt * BNT);
}

// ---------------- combine splitK partials + act + round ----------------
__global__ void combine_kernel(float* __restrict__ wpre, float* __restrict__ apre,
                               float* __restrict__ vpre, float* __restrict__ gpre) {
    int t = blockIdx.x;
    for (int idx = threadIdx.x; idx < 512; idx += 256) {
        int gi, n, N, off;
        if (idx < 96)       { gi = 0; n = idx;       N = 96;  off = PW; }
        else if (idx < 192) { gi = 1; n = idx - 96;  N = 96;  off = PA; }
        else if (idx < 256) { gi = 2; n = idx - 192; N = 64;  off = PV; }
        else                { gi = 3; n = idx - 256; N = 256; off = PG; }
        float s = 0.f;
#pragma unroll
        for (int kz = 0; kz < 4; kz++)
            s += g_part[off + ((size_t)kz * TT + t) * N + n];
        float r;
        if (gi == 0) r = tf32r(tanhf(s));
        else if (gi == 3) r = tf32r(1.f / (1.f + expf(-s)));
        else r = tf32r(s);
        if (gi == 0) wpre[t * 96 + n] = r;
        else if (gi == 1) apre[t * 96 + n] = r;
        else if (gi == 2) vpre[t * 64 + n] = r;
        else gpre[t * 256 + n] = r;
    }
}

// ---------------- K5: per-head prep (warp per (t,h)) ----------------
__global__ void prep_kernel(float* __restrict__ k, const float* __restrict__ a,
                            float* __restrict__ v, const float* __restrict__ v_first,
                            const float* __restrict__ vmix,
                            const float* __restrict__ k_k, const float* __restrict__ k_a,
                            float* __restrict__ kk, float* __restrict__ kka) {
    int hb = blockIdx.x * 8 + (threadIdx.x >> 5);
    int t = hb >> 5, h = hb & 31;
    int l = threadIdx.x & 31;
    int base = t * HID + h * HEAD;
    int hb0 = h * HEAD + l, hb1 = h * HEAD + l + 32;
    float k0 = k[base + l], k1 = k[base + 32 + l];
    float q0 = k0 * k_k[hb0], q1 = k1 * k_k[hb1];
    float ss = warp_sum(q0 * q0 + q1 * q1);
    float inv = 1.f / fmaxf(sqrtf(ss), 1e-12f);
    q0 *= inv; q1 *= inv;
    kk[base + l] = q0; kk[base + 32 + l] = q1;
    float a0 = a[base + l], a1 = a[base + 32 + l];
    kka[base + l] = q0 * a0; kka[base + 32 + l] = q1 * a1;
    k[base + l]      = k0 * (1.f + (a0 - 1.f) * k_a[hb0]);
    k[base + 32 + l] = k1 * (1.f + (a1 - 1.f) * k_a[hb1]);
    float v0 = v[base + l], v1 = v[base + 32 + l];
    v[base + l]      = v0 + (v_first[base + l]      - v0) * vmix[base + l];
    v[base + 32 + l] = v1 + (v_first[base + 32 + l] - v1) * vmix[base + 32 + l];
}

// ---------------- K6: recurrence, 4 steps per barrier ----------------
__device__ __forceinline__ float rec_load(int idx, int gb,
        const float* __restrict__ wv, const float* __restrict__ kkv,
        const float* __restrict__ kkav, const float* __restrict__ kv,
        const float* __restrict__ vv, const float* __restrict__ rv) {
    int arr = idx >> 6, j = idx & 63;
    const float* p;
    switch (arr) {
        case 0: p = wv; break;
        case 1: p = kkv; break;
        case 2: p = kkav; break;
        case 3: p = kv; break;
        case 4: p = vv; break;
        default: p = rv; break;
    }
    return p[gb + j];
}

__device__ __forceinline__ float rec_step(const float* __restrict__ b,
                                          u64* s2, int row, int cb) {
    const u64* w2v = (const u64*)(b + cb);
    const u64* kk2 = (const u64*)(b + 64 + cb);
    const u64* a2v = (const u64*)(b + 128 + cb);
    const u64* k2v = (const u64*)(b + 192 + cb);
    const u64* r2v = (const u64*)(b + 320 + cb);
    u64 sA = mul2(s2[0], kk2[0]);
    u64 sB = mul2(s2[1], kk2[1]);
#pragma unroll
    for (int i = 2; i < 8; i += 2) {
        sA = fma2(s2[i], kk2[i], sA);
        sB = fma2(s2[i + 1], kk2[i + 1], sB);
    }
    u64 sT = add2(sA, sB);
    float2 su = unpk(sT);
    float sab = su.x + su.y;
    sab += __shfl_xor_sync(0xffffffffu, sab, 1);
    sab += __shfl_xor_sync(0xffffffffu, sab, 2);
    u64 msab = dup2(-sab);
    u64 v2 = dup2(b[256 + row]);
    u64 yA = 0, yB = 0;
#pragma unroll
    for (int i = 0; i < 8; i += 2) {
        u64 t0 = fma2(msab, a2v[i], mul2(v2, k2v[i]));
        u64 t1 = fma2(msab, a2v[i + 1], mul2(v2, k2v[i + 1]));
        s2[i] = fma2(s2[i], w2v[i], t0);
        s2[i + 1] = fma2(s2[i + 1], w2v[i + 1], t1);
        if (i == 0) { yA = mul2(s2[0], r2v[0]); yB = mul2(s2[1], r2v[1]); }
        else { yA = fma2(s2[i], r2v[i], yA); yB = fma2(s2[i + 1], r2v[i + 1], yB); }
    }
    float2 yu = unpk(add2(yA, yB));
    float yy = yu.x + yu.y;
    yy += __shfl_xor_sync(0xffffffffu, yy, 1);
    yy += __shfl_xor_sync(0xffffffffu, yy, 2);
    return yy;
}

__global__ void __launch_bounds__(256) recur_kernel(
        const float* __restrict__ S0,
        const float* __restrict__ wv, const float* __restrict__ kkv,
        const float* __restrict__ kkav, const float* __restrict__ kv,
        const float* __restrict__ vv, const float* __restrict__ rv,
        float* __restrict__ yout, float* __restrict__ S_out) {
    __shared__ __align__(16) float sh[2][4][384];
    int h = blockIdx.x;
    int tid = threadIdx.x;
    int row = tid >> 2;
    int q = tid & 3;
    int cb = q * 16;
    u64 s2[8];
    {
        const u64* sp = (const u64*)(S0 + h * 4096 + row * 64 + cb);
#pragma unroll
        for (int i = 0; i < 8; i++) s2[i] = sp[i];
    }
    int base0 = h * HEAD;
    bool lo = (tid < 128);

    // pipeline registers: A = steps t0..t0+3 of current iter, B = t0+4..t0+7
    float A0[4], A1[4], B0[4], B1[4];
#pragma unroll
    for (int s = 0; s < 4; s++) {
        A0[s] = rec_load(tid, s * HID + base0, wv, kkv, kkav, kv, vv, rv);
        A1[s] = lo ? rec_load(tid + 256, s * HID + base0, wv, kkv, kkav, kv, vv, rv) : 0.f;
        B0[s] = rec_load(tid, (4 + s) * HID + base0, wv, kkv, kkav, kv, vv, rv);
        B1[s] = lo ? rec_load(tid + 256, (4 + s) * HID + base0, wv, kkv, kkav, kv, vv, rv) : 0.f;
    }

    for (int it2 = 0; it2 < TT / 8; it2++) {
        int t0 = it2 * 8;
        // ---- half A: steps t0..t0+3 ----
#pragma unroll
        for (int s = 0; s < 4; s++) {
            sh[0][s][tid] = A0[s];
            if (lo) sh[0][s][tid + 256] = A1[s];
        }
        __syncthreads();
        {
            int tl = t0 + 8;                  // A-half of it2+1 (FIX: was +16)
            if (tl < TT) {
#pragma unroll
                for (int s = 0; s < 4; s++) {
                    A0[s] = rec_load(tid, (tl + s) * HID + base0, wv, kkv, kkav, kv, vv, rv);
                    if (lo) A1[s] = rec_load(tid + 256, (tl + s) * HID + base0, wv, kkv, kkav, kv, vv, rv);
                }
            }
        }
#pragma unroll
        for (int s = 0; s < 4; s++) {
            float yy = rec_step(sh[0][s], s2, row, cb);
            if (q == 0) yout[(t0 + s) * HID + base0 + row] = yy;
        }
        // ---- half B: steps t0+4..t0+7 ----
#pragma unroll
        for (int s = 0; s < 4; s++) {
            sh[1][s][tid] = B0[s];
            if (lo) sh[1][s][tid + 256] = B1[s];
        }
        __syncthreads();
        {
            int tl = t0 + 12;                 // B-half of it2+1 (FIX: was +20)
            if (tl < TT) {
#pragma unroll
                for (int s = 0; s < 4; s++) {
                    B0[s] = rec_load(tid, (tl + s) * HID + base0, wv, kkv, kkav, kv, vv, rv);
                    if (lo) B1[s] = rec_load(tid + 256, (tl + s) * HID + base0, wv, kkv, kkav, kv, vv, rv);
                }
            }
        }
#pragma unroll
        for (int s = 0; s < 4; s++) {
            float yy = rec_step(sh[1][s], s2, row, cb);
            if (q == 0) yout[(t0 + 4 + s) * HID + base0 + row] = yy;
        }
    }
    u64* so = (u64*)(S_out + h * 4096 + row * 64 + cb);
#pragma unroll
    for (int i = 0; i < 8; i++) so[i] = s2[i];
}

// ---------------- K7: per-head LN + rkv + gate ----------------
__global__ void post_kernel(const float* __restrict__ y, const float* __restrict__ r,
                            const float* __restrict__ k, const float* __restrict__ v,
                            const float* __restrict__ g, const float* __restrict__ r_k,
                            const float* __restrict__ lnw, const float* __restrict__ lnb,
                            float* __restrict__ z) {
    int hb = blockIdx.x * 8 + (threadIdx.x >> 5);
    int t = hb >> 5, h = hb & 31;
    int l = threadIdx.x & 31;
    int base = t * HID + h * HEAD;
    int hb0 = h * HEAD + l, hb1 = h * HEAD + l + 32;
    float y0 = y[base + l], y1 = y[base + 32 + l];
    float mu = warp_sum(y0 + y1) * (1.f / HEAD);
    float d0 = y0 - mu, d1 = y1 - mu;
    float var = warp_sum(d0 * d0 + d1 * d1) * (1.f / HEAD);
    float rs = rsqrtf(var + 0.00064f);
    float yn0 = d0 * rs * lnw[hb0] + lnb[hb0];
    float yn1 = d1 * rs * lnw[hb1] + lnb[hb1];
    float dot = warp_sum(r[base + l] * k[base + l] * r_k[hb0] +
                         r[base + 32 + l] * k[base + 32 + l] * r_k[hb1]);
    z[base + l]      = tf32r((yn0 + dot * v[base + l])      * g[base + l]);
    z[base + 32 + l] = tf32r((yn1 + dot * v[base + 32 + l]) * g[base + 32 + l]);
}

// ---------------- copy ----------------
__global__ void copy4_kernel(const float4* __restrict__ src, float4* __restrict__ dst, int n4) {
    int i = blockIdx.x * blockDim.x + threadIdx.x;
    if (i < n4) dst[i] = src[i];
}

// ---------------- launch ----------------
extern "C" void kernel_launch(void* const* d_in, const int* in_sizes, int n_in,
                              void* d_out, int out_size) {
    const float* x       = (const float*)d_in[0];
    const float* state1  = (const float*)d_in[1];
    const float* state2  = (const float*)d_in[2];
    const float* v_first = (const float*)d_in[3];
    const float* ln1_w   = (const float*)d_in[4];
    const float* ln1_b   = (const float*)d_in[5];
    const float* x_r     = (const float*)d_in[6];
    const float* x_w     = (const float*)d_in[7];
    const float* x_k     = (const float*)d_in[8];
    const float* x_v     = (const float*)d_in[9];
    const float* x_a     = (const float*)d_in[10];
    const float* x_g     = (const float*)d_in[11];
    const float* Wr      = (const float*)d_in[12];
    const float* Wk      = (const float*)d_in[13];
    const float* Wv      = (const float*)d_in[14];
    const float* Wo      = (const float*)d_in[15];
    const float* w0      = (const float*)d_in[16];
    const float* w1      = (const float*)d_in[17];
    const float* w2      = (const float*)d_in[18];
    const float* a0      = (const float*)d_in[19];
    const float* a1      = (const float*)d_in[20];
    const float* a2      = (const float*)d_in[21];
    const float* v0      = (const float*)d_in[22];
    const float* v1      = (const float*)d_in[23];
    const float* v2      = (const float*)d_in[24];
    const float* g1      = (const float*)d_in[25];
    const float* g2      = (const float*)d_in[26];
    const float* k_k     = (const float*)d_in[27];
    const float* k_a     = (const float*)d_in[28];
    const float* r_k     = (const float*)d_in[29];
    const float* ln_x_w  = (const float*)d_in[30];
    const float* ln_x_b  = (const float*)d_in[31];

    float* out = (float*)d_out;
    float* out_main   = out;
    float* out_state1 = out + 2097152;
    float* out_S      = out + 2097152 + 2048;
    float* out_vfirst = out + 2097152 + 2048 + 131072;

    float *p_mix, *p_part;
    float *p_r, *p_k, *p_v, *p_w, *p_a, *p_g, *p_vmix, *p_kk, *p_kka, *p_y, *p_z;
    float *p_wpre, *p_apre, *p_vpre, *p_gpre;
    cudaGetSymbolAddress((void**)&p_mix, g_mix);
    cudaGetSymbolAddress((void**)&p_part, g_part);
    cudaGetSymbolAddress((void**)&p_r, g_r);
    cudaGetSymbolAddress((void**)&p_k, g_k);
    cudaGetSymbolAddress((void**)&p_v, g_v);
    cudaGetSymbolAddress((void**)&p_w, g_w);
    cudaGetSymbolAddress((void**)&p_a, g_a);
    cudaGetSymbolAddress((void**)&p_g, g_g);
    cudaGetSymbolAddress((void**)&p_vmix, g_vmix);
    cudaGetSymbolAddress((void**)&p_kk, g_kk);
    cudaGetSymbolAddress((void**)&p_kka, g_kka);
    cudaGetSymbolAddress((void**)&p_y, g_y);
    cudaGetSymbolAddress((void**)&p_z, g_z);
    cudaGetSymbolAddress((void**)&p_wpre, g_wpre);
    cudaGetSymbolAddress((void**)&p_apre, g_apre);
    cudaGetSymbolAddress((void**)&p_vpre, g_vpre);
    cudaGetSymbolAddress((void**)&p_gpre, g_gpre);

    float* mixp[6];
    for (int i = 0; i < 6; i++) mixp[i] = p_mix + (size_t)i * TT * HID;

    // K1: LN + token shift
    ln_shift_kernel<<<TT, 256>>>(x, state1, ln1_w, ln1_b,
                                 x_r, x_w, x_k, x_v, x_a, x_g, out_state1);

    // merged stage-1 splitK + 3 projections (one launch, 544 CTAs)
    BatchM bm;
    bm.A[0] = mixp[1]; bm.B[0] = w1; bm.C[0] = p_part + PW; bm.N[0] = 96;
    bm.A[1] = mixp[4]; bm.B[1] = a1; bm.C[1] = p_part + PA; bm.N[1] = 96;
    bm.A[2] = mixp[3]; bm.B[2] = v1; bm.C[2] = p_part + PV; bm.N[2] = 64;
    bm.A[3] = mixp[5]; bm.B[3] = g1; bm.C[3] = p_part + PG; bm.N[3] = 256;
    bm.A[4] = mixp[0]; bm.B[4] = Wr; bm.C[4] = p_r; bm.N[4] = HID;
    bm.A[5] = mixp[2]; bm.B[5] = Wk; bm.C[5] = p_k; bm.N[5] = HID;
    bm.A[6] = mixp[3]; bm.B[6] = Wv; bm.C[6] = p_v; bm.N[6] = HID;
    gemm_merged<<<dim3(68, 8), 256>>>(bm);

    // combine stage-1 partials
    combine_kernel<<<TT, 256>>>(p_wpre, p_apre, p_vpre, p_gpre);

    // stage-2, batched (one launch, 512 CTAs)
    BatchS2 b2;
    b2.A[0] = p_wpre; b2.B[0] = w2; b2.bias[0] = w0;      b2.C[0] = p_w;    b2.K[0] = 96;  b2.act[0] = 3;
    b2.A[1] = p_apre; b2.B[1] = a2; b2.bias[1] = a0;      b2.C[1] = p_a;    b2.K[1] = 96;  b2.act[1] = 2;
    b2.A[2] = p_vpre; b2.B[2] = v2; b2.bias[2] = v0;      b2.C[2] = p_vmix; b2.K[2] = 64;  b2.act[2] = 2;
    b2.A[3] = p_gpre; b2.B[3] = g2; b2.bias[3] = nullptr; b2.C[3] = p_g;    b2.K[3] = 256; b2.act[3] = 0;
    gemm_s2<<<dim3(64, 8), 256>>>(b2);

    // prep, recurrence, post
    prep_kernel<<<TT * NH / 8, 256>>>(p_k, p_a, p_v, v_first, p_vmix, k_k, k_a, p_kk, p_kka);
    recur_kernel<<<NH, 256>>>(state2, p_w, p_kk, p_kka, p_k, p_v, p_r, p_y, out_S);
    post_kernel<<<TT * NH / 8, 256>>>(p_y, p_r, p_k, p_v, p_g, r_k, ln_x_w, ln_x_b, p_z);

    // out = x + z @ Wo (single-op batch)
    Batch3 bo;
    bo.A[0] = p_z; bo.B[0] = Wo; bo.Cadd[0] = x; bo.C[0] = out_main;
    bo.A[1] = bo.A[0]; bo.B[1] = bo.B[0]; bo.Cadd[1] = nullptr; bo.C[1] = bo.C[0];
    bo.A[2] = bo.A[0]; bo.B[2] = bo.B[0]; bo.Cadd[2] = nullptr; bo.C[2] = bo.C[0];
    gemm_proj<<<dim3(16, 8, 1), 256>>>(bo);

    // v_first passthrough
    copy4_kernel<<<(524288 + 255) / 256, 256>>>((const float4*)v_first, (float4*)out_vfirst, 524288);

    (void)in_sizes; (void)n_in; (void)out_size;
}